// round 13
// baseline (speedup 1.0000x reference)
#include <cuda_runtime.h>
#include <cuda_bf16.h>
#include <math.h>
#include <stdint.h>

#define T_DIM 256
#define B_DIM 128
#define INP_DIM 768
#define HID 512
#define OUT_DIM 768
#define NL 4
#define G4 (4 * HID)            // 2048
#define ROWS (T_DIM * B_DIM)    // 32768
#define STATE (B_DIM * HID)     // 65536

#define NBLK 128                // persistent recurrence grid (<= SM count)
#define NGRP 4                  // independent barrier groups (one per bb)
#define GRP_BLKS 32             // blocks per group
#define GS 24                   // ff-gemm SMEM row stride (floats)

// recurrence chunked SMEM row stride (u32). 528*4 = 2112 B, 2112 mod 128 = 64
// -> every LDS.128 phase (8 lanes) conflict-free.
#define RSTR 528
#define GXS 36                  // gate-exchange stride (floats)

// ---------------- scratch (static device globals: no allocation) ----------------
__device__ float g_seqA[ROWS * HID];
__device__ float g_seqB[ROWS * HID];
__device__ float g_gates[ROWS * G4];
__device__ float g_outp[ROWS * OUT_DIM];
__device__ uint32_t g_hpack[STATE];      // h packed as (bf16 hi | bf16 lo << 16)

// per-group barrier state, 128B apart (32 u32 stride)
__device__ unsigned int g_bar_cnt4[NGRP * 32];
__device__ unsigned int g_bar_gen4[NGRP * 32];

// ---------------- tf32 helpers (FF GEMM) ----------------
__device__ __forceinline__ uint32_t f2tf(float f) {
    uint32_t u;
    asm("cvt.rna.tf32.f32 %0, %1;" : "=r"(u) : "f"(f));
    return u;
}
__device__ __forceinline__ void st8tf_ilv(float* p, float4 v0, float4 v1) {
    float4 t0, t1;
    t0.x = __uint_as_float(f2tf(v0.x));
    t0.y = __uint_as_float(f2tf(v1.x));
    t0.z = __uint_as_float(f2tf(v0.y));
    t0.w = __uint_as_float(f2tf(v1.y));
    t1.x = __uint_as_float(f2tf(v0.z));
    t1.y = __uint_as_float(f2tf(v1.z));
    t1.z = __uint_as_float(f2tf(v0.w));
    t1.w = __uint_as_float(f2tf(v1.w));
    *(float4*)p = t0;
    *(float4*)(p + 4) = t1;
}
__device__ __forceinline__ void mma8(float& c0, float& c1, float& c2, float& c3,
                                     uint32_t a0, uint32_t a1, uint32_t a2, uint32_t a3,
                                     uint32_t b0, uint32_t b1) {
    asm volatile("mma.sync.aligned.m16n8k8.row.col.f32.tf32.tf32.f32 "
                 "{%0,%1,%2,%3}, {%4,%5,%6,%7}, {%8,%9}, {%0,%1,%2,%3};"
                 : "+f"(c0), "+f"(c1), "+f"(c2), "+f"(c3)
                 : "r"(a0), "r"(a1), "r"(a2), "r"(a3), "r"(b0), "r"(b1));
}

// ---------------- bf16 helpers (recurrence) ----------------
__device__ __forceinline__ void mma16bf(float& c0, float& c1, float& c2, float& c3,
                                        uint32_t a0, uint32_t a1, uint32_t a2, uint32_t a3,
                                        uint32_t b0, uint32_t b1) {
    asm volatile("mma.sync.aligned.m16n8k16.row.col.f32.bf16.bf16.f32 "
                 "{%0,%1,%2,%3}, {%4,%5,%6,%7}, {%8,%9}, {%0,%1,%2,%3};"
                 : "+f"(c0), "+f"(c1), "+f"(c2), "+f"(c3)
                 : "r"(a0), "r"(a1), "r"(a2), "r"(a3), "r"(b0), "r"(b1));
}
__device__ __forceinline__ uint32_t split_pair(float a, float b, uint32_t& lo) {
    __nv_bfloat16 ah = __float2bfloat16_rn(a);
    __nv_bfloat16 bh = __float2bfloat16_rn(b);
    __nv_bfloat16 al = __float2bfloat16_rn(a - __bfloat162float(ah));
    __nv_bfloat16 bl = __float2bfloat16_rn(b - __bfloat162float(bh));
    lo = (uint32_t)__bfloat16_as_ushort(al) | ((uint32_t)__bfloat16_as_ushort(bl) << 16);
    return (uint32_t)__bfloat16_as_ushort(ah) | ((uint32_t)__bfloat16_as_ushort(bh) << 16);
}
__device__ __forceinline__ uint32_t hpk(float h) {
    __nv_bfloat16 hi = __float2bfloat16_rn(h);
    __nv_bfloat16 lo = __float2bfloat16_rn(h - __bfloat162float(hi));
    return (uint32_t)__bfloat16_as_ushort(hi) | ((uint32_t)__bfloat16_as_ushort(lo) << 16);
}

// Build 4 16B chunks {hi(tq),hi(tq+4),lo(tq),lo(tq+4)} from 16 fp32 values.
__device__ __forceinline__ void make_chunks_f32(const float* v, uint4* out) {
    uint32_t hi[8], lo[8];
#pragma unroll
    for (int p = 0; p < 8; p++) hi[p] = split_pair(v[2 * p], v[2 * p + 1], lo[p]);
#pragma unroll
    for (int tq = 0; tq < 4; tq++) {
        out[tq].x = hi[tq];
        out[tq].y = hi[tq + 4];
        out[tq].z = lo[tq];
        out[tq].w = lo[tq + 4];
    }
}
// Same from 16 hpack-packed u32 values (hi|lo<<16).
__device__ __forceinline__ void make_chunks_pk(const uint32_t* w, uint4* out) {
#pragma unroll
    for (int tq = 0; tq < 4; tq++) {
        const uint32_t a = w[2 * tq],     b = w[2 * tq + 1];
        const uint32_t c = w[2 * tq + 8], d = w[2 * tq + 9];
        out[tq].x = __byte_perm(a, b, 0x5410);
        out[tq].y = __byte_perm(c, d, 0x5410);
        out[tq].z = __byte_perm(a, b, 0x7632);
        out[tq].w = __byte_perm(c, d, 0x7632);
    }
}

// ============================================================================
// tf32 tensor-core GEMM:  C[M,N] = A[M,K] @ W[N,K]^T + bias1 (+ bias2)
// Block tile 128x256, 8 warps (2m x 4n), warp tile 64x64, k-chunk 16.
// Per k16-chunk per warp: 32 LDS.64 + 64 HMMA (2x the HMMA:LDS ratio of the
// old 64x32 warp tile). Dynamic SMEM 73.7 KB, 2-stage double buffering.
// Requires M%128==0, N%256==0 (true: N in {512, 2048, 768}).
// Per-element k-summation order identical to the previous version.
// ============================================================================
__global__ __launch_bounds__(256) void gemm_tf32(
    const float* __restrict__ A, const float* __restrict__ W,
    const float* __restrict__ bias1, const float* __restrict__ bias2,
    float* __restrict__ C, int K, int N, int xremap)
{
    extern __shared__ float gsm[];
    float* As = gsm;                    // [2][128*GS]
    float* Bs = gsm + 2 * 128 * GS;     // [2][256*GS]

    const int m0 = blockIdx.x * 128;
    const int n0 = blockIdx.y * 256;
    const int tid = threadIdx.x;
    const int lane = tid & 31;
    const int warp = tid >> 5;
    const int gid = lane >> 2;
    const int tig = lane & 3;
    const int wm = (warp >> 2) * 64;    // 0 or 64
    const int wn = (warp & 3) * 64;     // 0,64,128,192

    // staging roles: A: 2 threads/row (8 floats each); B: 1 thread/row (16 floats)
    const int srow = tid >> 1;
    const int skoff = (tid & 1) * 8;
    int arow = m0 + srow;
    if (xremap) {
        const int b = arow & (B_DIM - 1);
        const int t = arow >> 7;
        arow = b * T_DIM + t;
    }
    const float* ag = A + (long)arow * K + skoff;
    const float* bg = W + (long)(n0 + tid) * K;
    const int asoff = srow * GS + skoff;
    const int bsoff = tid * GS;

    float acc[4][8][4];
#pragma unroll
    for (int i = 0; i < 4; i++)
#pragma unroll
        for (int j = 0; j < 8; j++)
#pragma unroll
            for (int v = 0; v < 4; v++) acc[i][j][v] = 0.f;

    // prologue: stage chunk 0
    {
        float4 pa0 = *(const float4*)(ag);
        float4 pa1 = *(const float4*)(ag + 4);
        float4 pb0 = *(const float4*)(bg);
        float4 pb1 = *(const float4*)(bg + 4);
        float4 pb2 = *(const float4*)(bg + 8);
        float4 pb3 = *(const float4*)(bg + 12);
        st8tf_ilv(&As[asoff], pa0, pa1);
        st8tf_ilv(&Bs[bsoff], pb0, pb1);
        st8tf_ilv(&Bs[bsoff + 8], pb2, pb3);
    }
    __syncthreads();

    const int nch = K >> 4;
    for (int c = 0; c < nch; c++) {
        const int s = c & 1;
        const bool more = (c + 1 < nch);
        float4 na0, na1, nb0, nb1, nb2, nb3;
        if (more) {
            const int ko = (c + 1) << 4;
            na0 = *(const float4*)(ag + ko);
            na1 = *(const float4*)(ag + ko + 4);
            nb0 = *(const float4*)(bg + ko);
            nb1 = *(const float4*)(bg + ko + 4);
            nb2 = *(const float4*)(bg + ko + 8);
            nb3 = *(const float4*)(bg + ko + 12);
        }
        const float* Asb = As + s * 128 * GS;
        const float* Bsb = Bs + s * 256 * GS;
#pragma unroll
        for (int ks = 0; ks < 16; ks += 8) {
            const int kb = ks + 2 * tig;
            float2 alo[4], ahi[4], bf[8];
#pragma unroll
            for (int i = 0; i < 4; i++) {
                const float* ap = &Asb[(wm + i * 16 + gid) * GS + kb];
                alo[i] = *(const float2*)ap;
                ahi[i] = *(const float2*)(ap + 8 * GS);
            }
#pragma unroll
            for (int j = 0; j < 8; j++)
                bf[j] = *(const float2*)&Bsb[(wn + j * 8 + gid) * GS + kb];
#pragma unroll
            for (int i = 0; i < 4; i++)
#pragma unroll
                for (int j = 0; j < 8; j++)
                    mma8(acc[i][j][0], acc[i][j][1], acc[i][j][2], acc[i][j][3],
                         __float_as_uint(alo[i].x), __float_as_uint(ahi[i].x),
                         __float_as_uint(alo[i].y), __float_as_uint(ahi[i].y),
                         __float_as_uint(bf[j].x), __float_as_uint(bf[j].y));
        }
        if (more) {
            float* Asn = As + (s ^ 1) * 128 * GS;
            float* Bsn = Bs + (s ^ 1) * 256 * GS;
            st8tf_ilv(&Asn[asoff], na0, na1);
            st8tf_ilv(&Bsn[bsoff], nb0, nb1);
            st8tf_ilv(&Bsn[bsoff + 8], nb2, nb3);
        }
        __syncthreads();
    }

    // epilogue: bias + float2 stores
#pragma unroll
    for (int j = 0; j < 8; j++) {
        const int n = n0 + wn + j * 8 + 2 * tig;
        float bz0 = bias1[n], bz1 = bias1[n + 1];
        if (bias2) { bz0 += bias2[n]; bz1 += bias2[n + 1]; }
#pragma unroll
        for (int i = 0; i < 4; i++) {
            const int m = m0 + wm + i * 16 + gid;
            float2 o1; o1.x = acc[i][j][0] + bz0; o1.y = acc[i][j][1] + bz1;
            float2 o2; o2.x = acc[i][j][2] + bz0; o2.y = acc[i][j][3] + bz1;
            *(float2*)(C + (long)m * N + n) = o1;
            *(float2*)(C + (long)(m + 8) * N + n) = o2;
        }
    }
}

#define GEMM_SMEM ((2 * 128 * GS + 2 * 256 * GS) * 4)   // 73,728 B

// ============================================================================
// Group barrier: 32 co-resident blocks sharing one bb (batch range).
// ============================================================================
__device__ __forceinline__ void group_barrier(int grp)
{
    __threadfence();
    __syncthreads();
    if (threadIdx.x == 0) {
        volatile unsigned int* genp = &g_bar_gen4[grp * 32];
        const unsigned g = *genp;
        const unsigned a = atomicAdd(&g_bar_cnt4[grp * 32], 1u);
        if (a == GRP_BLKS - 1) {
            g_bar_cnt4[grp * 32] = 0;
            __threadfence();
            *genp = g + 1u;
        } else {
            while (*genp == g) { }
        }
    }
    __syncthreads();
}

// ============================================================================
// Persistent LSTM layer (unchanged from R12, passing).
// ============================================================================
__global__ __launch_bounds__(512, 1) void lstm_layer_kernel(
    const float* __restrict__ h0, const float* __restrict__ c0,
    const float* __restrict__ Whh, const float* __restrict__ gates,
    float* __restrict__ seq, uint32_t* __restrict__ hpack,
    float* __restrict__ hT, float* __restrict__ cT)
{
    extern __shared__ uint32_t smem[];
    uint32_t* ws = smem;                       // phase 1: [64][RSTR]
    uint32_t* hs = smem;                       // phase 2: [32][RSTR]
    float*    gx = (float*)(smem + 32 * RSTR); // phase 2: [4][64][GXS]

    const int tid = threadIdx.x;
    const int lane = tid & 31;
    const int warp = tid >> 5;                 // 0..15
    const int g = warp & 3;                    // gate
    const int kq = warp >> 2;                  // k-quarter 0..3
    const int fg = lane >> 2;                  // fragment group 0..7
    const int tq = lane & 3;

    const int mb = blockIdx.x & 31;
    const int bb = blockIdx.x >> 5;            // barrier group
    const int m0 = mb * 16;
    const int b0 = bb * 32;

    // ---- phase 1: stage W slice into SMEM chunk layout (one-time)
#pragma unroll
    for (int i = 0; i < 4; i++) {
        const int cell = tid + 512 * i;
        const int r = cell >> 5;               // local row 0..63
        const int ks = cell & 31;              // k-chunk 0..31
        const int wg = r >> 4, mli = r & 15;
        const float* wrow = Whh + (long)(wg * HID + m0 + mli) * HID + ks * 16;
        float v[16];
#pragma unroll
        for (int q = 0; q < 4; q++) *(float4*)(v + 4 * q) = *(const float4*)(wrow + 4 * q);
        uint4 ck[4];
        make_chunks_f32(v, ck);
        uint32_t* dst = ws + r * RSTR + ks * 16;
#pragma unroll
        for (int q = 0; q < 4; q++) *(uint4*)(dst + 4 * q) = ck[q];
    }
    __syncthreads();

    // ---- preload A fragments into registers (loop-invariant across t)
    const int ks0 = kq * 8;
    uint4 areg[8][2];
    {
        const uint32_t* wbase = ws + (g * 16) * RSTR;
#pragma unroll
        for (int i = 0; i < 8; i++) {
            const int off = (ks0 + i) * 16 + tq * 4;
            areg[i][0] = *(const uint4*)(wbase + fg * RSTR + off);
            areg[i][1] = *(const uint4*)(wbase + (fg + 8) * RSTR + off);
        }
    }
    __syncthreads();   // ws reads done; smem reused as hs/gx

    // activation roles: thread = (ml 0..15, bh 0..31) -> 1 batch
    const int ml = tid & 15;
    const int bh = tid >> 4;
    const int m = m0 + ml;
    const int b = b0 + bh;

    float creg = c0[(long)b * HID + m];

    for (int t = 0; t < T_DIM; t++) {
        // prefetch this step's precomputed gate contributions
        const float* pre = gates + (long)t * B_DIM * G4 + (long)b * G4 + m;
        float pg[4];
#pragma unroll
        for (int gg = 0; gg < 4; gg++)
            pg[gg] = __ldcg(pre + (gg << 9));

        // ---- stage h(t-1): 1024 cells / 512 threads
        if (t == 0) {
#pragma unroll
            for (int i = 0; i < 2; i++) {
                const int cell = tid + 512 * i;
                const int sb = cell >> 5;
                const int ks = cell & 31;
                const float* hrow = h0 + (long)(b0 + sb) * HID + ks * 16;
                float v[16];
#pragma unroll
                for (int q = 0; q < 4; q++) *(float4*)(v + 4 * q) = __ldcg((const float4*)(hrow + 4 * q));
                uint4 ck[4];
                make_chunks_f32(v, ck);
                uint32_t* dst = hs + sb * RSTR + ks * 16;
#pragma unroll
                for (int q = 0; q < 4; q++) *(uint4*)(dst + 4 * q) = ck[q];
            }
        } else {
#pragma unroll
            for (int i = 0; i < 2; i++) {
                const int cell = tid + 512 * i;
                const int sb = cell >> 5;
                const int ks = cell & 31;
                const uint32_t* hrow = hpack + (long)(b0 + sb) * HID + ks * 16;
                uint32_t u[16];
#pragma unroll
                for (int q = 0; q < 4; q++) *(uint4*)(u + 4 * q) = __ldcg((const uint4*)(hrow + 4 * q));
                uint4 ck[4];
                make_chunks_pk(u, ck);
                uint32_t* dst = hs + sb * RSTR + ks * 16;
#pragma unroll
                for (int q = 0; q < 4; q++) *(uint4*)(dst + 4 * q) = ck[q];
            }
        }
        __syncthreads();   // hs ready

        // ---- mma: warp computes gate g, k-quarter kq, all 32 batches
        float acc[4][4];
#pragma unroll
        for (int j = 0; j < 4; j++)
#pragma unroll
            for (int v = 0; v < 4; v++) acc[j][v] = 0.f;

#pragma unroll
        for (int i = 0; i < 8; i++) {
            const int off = (ks0 + i) * 16 + tq * 4;
            const uint4 A0 = areg[i][0];
            const uint4 A1 = areg[i][1];
#pragma unroll
            for (int j = 0; j < 4; j++) {
                const uint4 Bv = *(const uint4*)(hs + (8 * j + fg) * RSTR + off);
                mma16bf(acc[j][0], acc[j][1], acc[j][2], acc[j][3],
                        A0.x, A1.x, A0.y, A1.y, Bv.x, Bv.y);   // hi*hi
                mma16bf(acc[j][0], acc[j][1], acc[j][2], acc[j][3],
                        A0.x, A1.x, A0.y, A1.y, Bv.z, Bv.w);   // hi*lo
                mma16bf(acc[j][0], acc[j][1], acc[j][2], acc[j][3],
                        A0.z, A1.z, A0.w, A1.w, Bv.x, Bv.y);   // lo*hi
            }
        }

        // ---- write partial gates to this k-quarter's exchange plane
        float* gxp = gx + kq * (64 * GXS);
#pragma unroll
        for (int j = 0; j < 4; j++) {
            float2 lo2; lo2.x = acc[j][0]; lo2.y = acc[j][1];
            float2 hi2; hi2.x = acc[j][2]; hi2.y = acc[j][3];
            *(float2*)&gxp[(g * 16 + fg) * GXS + 8 * j + 2 * tq] = lo2;
            *(float2*)&gxp[(g * 16 + fg + 8) * GXS + 8 * j + 2 * tq] = hi2;
        }
        __syncthreads();

        // ---- activations: sum 4 k-quarter partials, update state, write h
        float gate[4];
#pragma unroll
        for (int gg = 0; gg < 4; gg++) {
            const int row = (gg * 16 + ml) * GXS + bh;
            gate[gg] = (gx[row] + gx[64 * GXS + row])
                     + (gx[2 * 64 * GXS + row] + gx[3 * 64 * GXS + row]);
        }

        const float gi = gate[0] + pg[0];
        const float gf = gate[1] + pg[1];
        const float gg = gate[2] + pg[2];
        const float go = gate[3] + pg[3];
        const float i_ = __fdividef(1.f, 1.f + __expf(-gi));
        const float f_ = __fdividef(1.f, 1.f + __expf(-gf));
        const float g_ = tanhf(gg);
        const float o_ = __fdividef(1.f, 1.f + __expf(-go));
        const float c = f_ * creg + i_ * g_;
        creg = c;
        const float h = o_ * tanhf(c);
        hpack[(long)b * HID + m] = hpk(h);
        seq[(long)t * STATE + (long)b * HID + m] = h;
        if (t == T_DIM - 1) {
            hT[(long)b * HID + m] = h;
            cT[(long)b * HID + m] = c;
        }

        group_barrier(bb);   // only the 32 blocks sharing this batch range
    }
}

// ============================================================================
// LayerNorm + (t,b)->(b,t) transpose (unchanged).
// ============================================================================
__global__ __launch_bounds__(256) void ln_out_kernel(
    const float* __restrict__ X, const float* __restrict__ gamma,
    const float* __restrict__ beta, float* __restrict__ out)
{
    const int row = blockIdx.x;
    const float* x = X + (long)row * OUT_DIM;
    const int tid = threadIdx.x;

    const float v0 = x[tid];
    const float v1 = x[tid + 256];
    const float v2 = x[tid + 512];

    __shared__ float red[8];
    __shared__ float s_mu, s_rs;

    float s = v0 + v1 + v2;
#pragma unroll
    for (int o = 16; o > 0; o >>= 1) s += __shfl_down_sync(0xffffffffu, s, o);
    if ((tid & 31) == 0) red[tid >> 5] = s;
    __syncthreads();
    if (tid == 0) {
        float tot = 0.f;
#pragma unroll
        for (int i = 0; i < 8; i++) tot += red[i];
        s_mu = tot * (1.f / OUT_DIM);
    }
    __syncthreads();
    const float mu = s_mu;
    const float d0 = v0 - mu, d1 = v1 - mu, d2 = v2 - mu;

    float q = d0 * d0 + d1 * d1 + d2 * d2;
#pragma unroll
    for (int o = 16; o > 0; o >>= 1) q += __shfl_down_sync(0xffffffffu, q, o);
    if ((tid & 31) == 0) red[tid >> 5] = q;
    __syncthreads();
    if (tid == 0) {
        float tot = 0.f;
#pragma unroll
        for (int i = 0; i < 8; i++) tot += red[i];
        s_rs = rsqrtf(tot * (1.f / OUT_DIM) + 1e-5f);
    }
    __syncthreads();
    const float rs = s_rs;

    const int b = row & (B_DIM - 1);
    const int t = row >> 7;
    float* o = out + (long)(b * T_DIM + t) * OUT_DIM;
    o[tid]       = d0 * rs * gamma[tid]       + beta[tid];
    o[tid + 256] = d1 * rs * gamma[tid + 256] + beta[tid + 256];
    o[tid + 512] = d2 * rs * gamma[tid + 512] + beta[tid + 512];
}

// ============================================================================
extern "C" void kernel_launch(void* const* d_in, const int* in_sizes, int n_in,
                              void* d_out, int out_size)
{
    const float* x     = (const float*)d_in[0];
    const float* h0    = (const float*)d_in[1];
    const float* c0    = (const float*)d_in[2];
    const float* W_in  = (const float*)d_in[3];
    const float* b_in  = (const float*)d_in[4];
    const float* W_ih  = (const float*)d_in[5];
    const float* W_hh  = (const float*)d_in[6];
    const float* b_ih  = (const float*)d_in[7];
    const float* b_hh  = (const float*)d_in[8];
    const float* W_out = (const float*)d_in[9];
    const float* b_out = (const float*)d_in[10];
    const float* ln_g  = (const float*)d_in[11];
    const float* ln_b  = (const float*)d_in[12];
    float* out = (float*)d_out;

    float *seqA, *seqB, *gates, *outp;
    uint32_t* hpack;
    cudaGetSymbolAddress((void**)&seqA, g_seqA);
    cudaGetSymbolAddress((void**)&seqB, g_seqB);
    cudaGetSymbolAddress((void**)&gates, g_gates);
    cudaGetSymbolAddress((void**)&outp, g_outp);
    cudaGetSymbolAddress((void**)&hpack, g_hpack);

    const int ws_bytes = 64 * RSTR * 4;                           // 135168
    const int ph2_bytes = 32 * RSTR * 4 + 4 * 64 * GXS * 4;       // 104448
    const int lstm_smem = ws_bytes > ph2_bytes ? ws_bytes : ph2_bytes;
    cudaFuncSetAttribute(lstm_layer_kernel,
                         cudaFuncAttributeMaxDynamicSharedMemorySize, lstm_smem);
    cudaFuncSetAttribute(gemm_tf32,
                         cudaFuncAttributeMaxDynamicSharedMemorySize, GEMM_SMEM);

    const long OUT_ELEMS = (long)B_DIM * T_DIM * OUT_DIM;

    // 1) input projection with (b,t)->(t,b) transpose (tf32 TC)
    gemm_tf32<<<dim3(ROWS / 128, HID / 256), 256, GEMM_SMEM>>>(
        x, W_in, b_in, nullptr, seqA, INP_DIM, HID, 1);

    for (int l = 0; l < NL; l++) {
        const float* in = (l & 1) ? seqB : seqA;
        float* outSeq   = (l & 1) ? seqA : seqB;

        // 2a) parallel: gates = in @ W_ih[l]^T + b_ih[l] + b_hh[l] (tf32 TC)
        gemm_tf32<<<dim3(ROWS / 128, G4 / 256), 256, GEMM_SMEM>>>(
            in, W_ih + (long)l * G4 * HID, b_ih + l * G4, b_hh + l * G4,
            gates, HID, G4, 0);

        // 2b) serial recurrence: persistent, bf16-split TC, 16 warps
        lstm_layer_kernel<<<NBLK, 512, lstm_smem>>>(
            h0 + (long)l * STATE, c0 + (long)l * STATE,
            W_hh + (long)l * G4 * HID, gates, outSeq, hpack,
            out + OUT_ELEMS + (long)l * STATE,
            out + OUT_ELEMS + (long)NL * STATE + (long)l * STATE);
    }

    // 3) output projection (tf32 TC)
    gemm_tf32<<<dim3(ROWS / 128, OUT_DIM / 256), 256, GEMM_SMEM>>>(
        seqA, W_out, b_out, nullptr, outp, HID, OUT_DIM, 0);

    // 4) layernorm + transpose into d_out
    ln_out_kernel<<<ROWS, 256>>>(outp, ln_g, ln_b, out);
}

// round 14
// speedup vs baseline: 1.0947x; 1.0947x over previous
#include <cuda_runtime.h>
#include <cuda_bf16.h>
#include <math.h>
#include <stdint.h>

#define T_DIM 256
#define B_DIM 128
#define INP_DIM 768
#define HID 512
#define OUT_DIM 768
#define NL 4
#define G4 (4 * HID)            // 2048
#define ROWS (T_DIM * B_DIM)    // 32768
#define STATE (B_DIM * HID)     // 65536

#define NBLK 128                // persistent recurrence grid (<= SM count)
#define NGRP 4                  // independent barrier groups (one per bb)
#define GRP_BLKS 32             // blocks per group
#define GS 24                   // ff-gemm SMEM row stride (floats)

// recurrence chunked SMEM row stride (u32). 528*4 = 2112 B, 2112 mod 128 = 64
// -> every LDS.128 phase (8 lanes) conflict-free.
#define RSTR 528
#define GXS 36                  // gate-exchange stride (floats)

// ---------------- scratch (static device globals: no allocation) ----------------
__device__ float g_seqA[ROWS * HID];
__device__ float g_seqB[ROWS * HID];
__device__ float g_gates[ROWS * G4];
__device__ float g_outp[ROWS * OUT_DIM];
__device__ uint32_t g_hpack[STATE];      // h packed as (bf16 hi | bf16 lo << 16)

// per-group barrier state, 128B apart (32 u32 stride)
__device__ unsigned int g_bar_cnt4[NGRP * 32];
__device__ unsigned int g_bar_gen4[NGRP * 32];

// ---------------- tf32 helpers (FF GEMM) ----------------
__device__ __forceinline__ uint32_t f2tf(float f) {
    uint32_t u;
    asm("cvt.rna.tf32.f32 %0, %1;" : "=r"(u) : "f"(f));
    return u;
}
__device__ __forceinline__ void st8tf_ilv(float* p, float4 v0, float4 v1) {
    float4 t0, t1;
    t0.x = __uint_as_float(f2tf(v0.x));
    t0.y = __uint_as_float(f2tf(v1.x));
    t0.z = __uint_as_float(f2tf(v0.y));
    t0.w = __uint_as_float(f2tf(v1.y));
    t1.x = __uint_as_float(f2tf(v0.z));
    t1.y = __uint_as_float(f2tf(v1.z));
    t1.z = __uint_as_float(f2tf(v0.w));
    t1.w = __uint_as_float(f2tf(v1.w));
    *(float4*)p = t0;
    *(float4*)(p + 4) = t1;
}
__device__ __forceinline__ void mma8(float& c0, float& c1, float& c2, float& c3,
                                     uint32_t a0, uint32_t a1, uint32_t a2, uint32_t a3,
                                     uint32_t b0, uint32_t b1) {
    asm volatile("mma.sync.aligned.m16n8k8.row.col.f32.tf32.tf32.f32 "
                 "{%0,%1,%2,%3}, {%4,%5,%6,%7}, {%8,%9}, {%0,%1,%2,%3};"
                 : "+f"(c0), "+f"(c1), "+f"(c2), "+f"(c3)
                 : "r"(a0), "r"(a1), "r"(a2), "r"(a3), "r"(b0), "r"(b1));
}

// ---------------- bf16 helpers (recurrence) ----------------
__device__ __forceinline__ void mma16bf(float& c0, float& c1, float& c2, float& c3,
                                        uint32_t a0, uint32_t a1, uint32_t a2, uint32_t a3,
                                        uint32_t b0, uint32_t b1) {
    asm volatile("mma.sync.aligned.m16n8k16.row.col.f32.bf16.bf16.f32 "
                 "{%0,%1,%2,%3}, {%4,%5,%6,%7}, {%8,%9}, {%0,%1,%2,%3};"
                 : "+f"(c0), "+f"(c1), "+f"(c2), "+f"(c3)
                 : "r"(a0), "r"(a1), "r"(a2), "r"(a3), "r"(b0), "r"(b1));
}
__device__ __forceinline__ uint32_t split_pair(float a, float b, uint32_t& lo) {
    __nv_bfloat16 ah = __float2bfloat16_rn(a);
    __nv_bfloat16 bh = __float2bfloat16_rn(b);
    __nv_bfloat16 al = __float2bfloat16_rn(a - __bfloat162float(ah));
    __nv_bfloat16 bl = __float2bfloat16_rn(b - __bfloat162float(bh));
    lo = (uint32_t)__bfloat16_as_ushort(al) | ((uint32_t)__bfloat16_as_ushort(bl) << 16);
    return (uint32_t)__bfloat16_as_ushort(ah) | ((uint32_t)__bfloat16_as_ushort(bh) << 16);
}
__device__ __forceinline__ uint32_t hpk(float h) {
    __nv_bfloat16 hi = __float2bfloat16_rn(h);
    __nv_bfloat16 lo = __float2bfloat16_rn(h - __bfloat162float(hi));
    return (uint32_t)__bfloat16_as_ushort(hi) | ((uint32_t)__bfloat16_as_ushort(lo) << 16);
}

// Build 4 16B chunks {hi(tq),hi(tq+4),lo(tq),lo(tq+4)} from 16 fp32 values.
__device__ __forceinline__ void make_chunks_f32(const float* v, uint4* out) {
    uint32_t hi[8], lo[8];
#pragma unroll
    for (int p = 0; p < 8; p++) hi[p] = split_pair(v[2 * p], v[2 * p + 1], lo[p]);
#pragma unroll
    for (int tq = 0; tq < 4; tq++) {
        out[tq].x = hi[tq];
        out[tq].y = hi[tq + 4];
        out[tq].z = lo[tq];
        out[tq].w = lo[tq + 4];
    }
}
// Same from 16 hpack-packed u32 values (hi|lo<<16).
__device__ __forceinline__ void make_chunks_pk(const uint32_t* w, uint4* out) {
#pragma unroll
    for (int tq = 0; tq < 4; tq++) {
        const uint32_t a = w[2 * tq],     b = w[2 * tq + 1];
        const uint32_t c = w[2 * tq + 8], d = w[2 * tq + 9];
        out[tq].x = __byte_perm(a, b, 0x5410);
        out[tq].y = __byte_perm(c, d, 0x5410);
        out[tq].z = __byte_perm(a, b, 0x7632);
        out[tq].w = __byte_perm(c, d, 0x7632);
    }
}

// ============================================================================
// tf32 tensor-core GEMM, 128x128 block tile, 2-stage SMEM double buffering.
// EXACT restore of the R12 configuration (measured 622 us on the gates GEMM):
// 8 warps (2m x 4n), warp tile 64x32, static SMEM 49 KB, ~120 regs ->
// 2 blocks/SM (16 warps) — the occupancy the wide-tile R13 variant lost.
// ============================================================================
__global__ __launch_bounds__(256) void gemm_tf32(
    const float* __restrict__ A, const float* __restrict__ W,
    const float* __restrict__ bias1, const float* __restrict__ bias2,
    float* __restrict__ C, int K, int N, int xremap)
{
    __shared__ __align__(16) float As[2][128 * GS];
    __shared__ __align__(16) float Bs[2][128 * GS];

    const int m0 = blockIdx.x * 128;
    const int n0 = blockIdx.y * 128;
    const int tid = threadIdx.x;
    const int lane = tid & 31;
    const int warp = tid >> 5;
    const int gid = lane >> 2;
    const int tig = lane & 3;
    const int wm = (warp >> 2) * 64;
    const int wn = (warp & 3) * 32;

    const int srow = tid >> 1;
    const int skoff = (tid & 1) * 8;
    int arow = m0 + srow;
    if (xremap) {
        const int b = arow & (B_DIM - 1);
        const int t = arow >> 7;
        arow = b * T_DIM + t;
    }
    const float* ag = A + (long)arow * K + skoff;
    const float* bg = W + (long)(n0 + srow) * K + skoff;
    const int soff = srow * GS + skoff;

    float acc[4][4][4];
#pragma unroll
    for (int i = 0; i < 4; i++)
#pragma unroll
        for (int j = 0; j < 4; j++)
#pragma unroll
            for (int v = 0; v < 4; v++) acc[i][j][v] = 0.f;

    {
        float4 pa0 = *(const float4*)(ag);
        float4 pa1 = *(const float4*)(ag + 4);
        float4 pb0 = *(const float4*)(bg);
        float4 pb1 = *(const float4*)(bg + 4);
        st8tf_ilv(&As[0][soff], pa0, pa1);
        st8tf_ilv(&Bs[0][soff], pb0, pb1);
    }
    __syncthreads();

    const int nch = K >> 4;
    for (int c = 0; c < nch; c++) {
        const int s = c & 1;
        const bool more = (c + 1 < nch);
        float4 na0, na1, nb0, nb1;
        if (more) {
            const int ko = (c + 1) << 4;
            na0 = *(const float4*)(ag + ko);
            na1 = *(const float4*)(ag + ko + 4);
            nb0 = *(const float4*)(bg + ko);
            nb1 = *(const float4*)(bg + ko + 4);
        }
#pragma unroll
        for (int ks = 0; ks < 16; ks += 8) {
            const int kb = ks + 2 * tig;
            float2 alo[4], ahi[4], bf[4];
#pragma unroll
            for (int i = 0; i < 4; i++) {
                const float* ap = &As[s][(wm + i * 16 + gid) * GS + kb];
                alo[i] = *(const float2*)ap;
                ahi[i] = *(const float2*)(ap + 8 * GS);
            }
#pragma unroll
            for (int j = 0; j < 4; j++)
                bf[j] = *(const float2*)&Bs[s][(wn + j * 8 + gid) * GS + kb];
#pragma unroll
            for (int i = 0; i < 4; i++)
#pragma unroll
                for (int j = 0; j < 4; j++)
                    mma8(acc[i][j][0], acc[i][j][1], acc[i][j][2], acc[i][j][3],
                         __float_as_uint(alo[i].x), __float_as_uint(ahi[i].x),
                         __float_as_uint(alo[i].y), __float_as_uint(ahi[i].y),
                         __float_as_uint(bf[j].x), __float_as_uint(bf[j].y));
        }
        if (more) {
            st8tf_ilv(&As[s ^ 1][soff], na0, na1);
            st8tf_ilv(&Bs[s ^ 1][soff], nb0, nb1);
        }
        __syncthreads();
    }

#pragma unroll
    for (int j = 0; j < 4; j++) {
        const int n = n0 + wn + j * 8 + 2 * tig;
        float bz0 = bias1[n], bz1 = bias1[n + 1];
        if (bias2) { bz0 += bias2[n]; bz1 += bias2[n + 1]; }
#pragma unroll
        for (int i = 0; i < 4; i++) {
            const int m = m0 + wm + i * 16 + gid;
            float2 o1; o1.x = acc[i][j][0] + bz0; o1.y = acc[i][j][1] + bz1;
            float2 o2; o2.x = acc[i][j][2] + bz0; o2.y = acc[i][j][3] + bz1;
            *(float2*)(C + (long)m * N + n) = o1;
            *(float2*)(C + (long)(m + 8) * N + n) = o2;
        }
    }
}

// ============================================================================
// Group barrier: 32 co-resident blocks sharing one bb (batch range).
// ============================================================================
__device__ __forceinline__ void group_barrier(int grp)
{
    __threadfence();
    __syncthreads();
    if (threadIdx.x == 0) {
        volatile unsigned int* genp = &g_bar_gen4[grp * 32];
        const unsigned g = *genp;
        const unsigned a = atomicAdd(&g_bar_cnt4[grp * 32], 1u);
        if (a == GRP_BLKS - 1) {
            g_bar_cnt4[grp * 32] = 0;
            __threadfence();
            *genp = g + 1u;
        } else {
            while (*genp == g) { }
        }
    }
    __syncthreads();
}

// ============================================================================
// Persistent LSTM layer (R12 configuration, passing at 6.66e-4).
// 512 threads / 16 warps; warp = (gate, k-quarter); W fragments in registers.
// Trim vs R12: final timestep skips the group barrier (no later reader inside
// this launch; the kernel boundary orders hT/cT/seq for subsequent kernels).
// ============================================================================
__global__ __launch_bounds__(512, 1) void lstm_layer_kernel(
    const float* __restrict__ h0, const float* __restrict__ c0,
    const float* __restrict__ Whh, const float* __restrict__ gates,
    float* __restrict__ seq, uint32_t* __restrict__ hpack,
    float* __restrict__ hT, float* __restrict__ cT)
{
    extern __shared__ uint32_t smem[];
    uint32_t* ws = smem;                       // phase 1: [64][RSTR]
    uint32_t* hs = smem;                       // phase 2: [32][RSTR]
    float*    gx = (float*)(smem + 32 * RSTR); // phase 2: [4][64][GXS]

    const int tid = threadIdx.x;
    const int lane = tid & 31;
    const int warp = tid >> 5;                 // 0..15
    const int g = warp & 3;                    // gate
    const int kq = warp >> 2;                  // k-quarter 0..3
    const int fg = lane >> 2;                  // fragment group 0..7
    const int tq = lane & 3;

    const int mb = blockIdx.x & 31;
    const int bb = blockIdx.x >> 5;            // barrier group
    const int m0 = mb * 16;
    const int b0 = bb * 32;

    // ---- phase 1: stage W slice into SMEM chunk layout (one-time)
#pragma unroll
    for (int i = 0; i < 4; i++) {
        const int cell = tid + 512 * i;
        const int r = cell >> 5;               // local row 0..63
        const int ks = cell & 31;              // k-chunk 0..31
        const int wg = r >> 4, mli = r & 15;
        const float* wrow = Whh + (long)(wg * HID + m0 + mli) * HID + ks * 16;
        float v[16];
#pragma unroll
        for (int q = 0; q < 4; q++) *(float4*)(v + 4 * q) = *(const float4*)(wrow + 4 * q);
        uint4 ck[4];
        make_chunks_f32(v, ck);
        uint32_t* dst = ws + r * RSTR + ks * 16;
#pragma unroll
        for (int q = 0; q < 4; q++) *(uint4*)(dst + 4 * q) = ck[q];
    }
    __syncthreads();

    // ---- preload A fragments into registers (loop-invariant across t)
    const int ks0 = kq * 8;
    uint4 areg[8][2];
    {
        const uint32_t* wbase = ws + (g * 16) * RSTR;
#pragma unroll
        for (int i = 0; i < 8; i++) {
            const int off = (ks0 + i) * 16 + tq * 4;
            areg[i][0] = *(const uint4*)(wbase + fg * RSTR + off);
            areg[i][1] = *(const uint4*)(wbase + (fg + 8) * RSTR + off);
        }
    }
    __syncthreads();   // ws reads done; smem reused as hs/gx

    // activation roles: thread = (ml 0..15, bh 0..31) -> 1 batch
    const int ml = tid & 15;
    const int bh = tid >> 4;
    const int m = m0 + ml;
    const int b = b0 + bh;

    float creg = c0[(long)b * HID + m];
    const float* preb = gates + (long)b * G4 + m;

    for (int t = 0; t < T_DIM; t++) {
        // prefetch this step's precomputed gate contributions
        const float* pre = preb + (long)t * B_DIM * G4;
        float pg[4];
#pragma unroll
        for (int gg = 0; gg < 4; gg++)
            pg[gg] = __ldcg(pre + (gg << 9));

        // ---- stage h(t-1): 1024 cells / 512 threads
        if (t == 0) {
#pragma unroll
            for (int i = 0; i < 2; i++) {
                const int cell = tid + 512 * i;
                const int sb = cell >> 5;
                const int ks = cell & 31;
                const float* hrow = h0 + (long)(b0 + sb) * HID + ks * 16;
                float v[16];
#pragma unroll
                for (int q = 0; q < 4; q++) *(float4*)(v + 4 * q) = __ldcg((const float4*)(hrow + 4 * q));
                uint4 ck[4];
                make_chunks_f32(v, ck);
                uint32_t* dst = hs + sb * RSTR + ks * 16;
#pragma unroll
                for (int q = 0; q < 4; q++) *(uint4*)(dst + 4 * q) = ck[q];
            }
        } else {
#pragma unroll
            for (int i = 0; i < 2; i++) {
                const int cell = tid + 512 * i;
                const int sb = cell >> 5;
                const int ks = cell & 31;
                const uint32_t* hrow = hpack + (long)(b0 + sb) * HID + ks * 16;
                uint32_t u[16];
#pragma unroll
                for (int q = 0; q < 4; q++) *(uint4*)(u + 4 * q) = __ldcg((const uint4*)(hrow + 4 * q));
                uint4 ck[4];
                make_chunks_pk(u, ck);
                uint32_t* dst = hs + sb * RSTR + ks * 16;
#pragma unroll
                for (int q = 0; q < 4; q++) *(uint4*)(dst + 4 * q) = ck[q];
            }
        }
        __syncthreads();   // hs ready

        // ---- mma: warp computes gate g, k-quarter kq, all 32 batches
        float acc[4][4];
#pragma unroll
        for (int j = 0; j < 4; j++)
#pragma unroll
            for (int v = 0; v < 4; v++) acc[j][v] = 0.f;

#pragma unroll
        for (int i = 0; i < 8; i++) {
            const int off = (ks0 + i) * 16 + tq * 4;
            const uint4 A0 = areg[i][0];
            const uint4 A1 = areg[i][1];
#pragma unroll
            for (int j = 0; j < 4; j++) {
                const uint4 Bv = *(const uint4*)(hs + (8 * j + fg) * RSTR + off);
                mma16bf(acc[j][0], acc[j][1], acc[j][2], acc[j][3],
                        A0.x, A1.x, A0.y, A1.y, Bv.x, Bv.y);   // hi*hi
                mma16bf(acc[j][0], acc[j][1], acc[j][2], acc[j][3],
                        A0.x, A1.x, A0.y, A1.y, Bv.z, Bv.w);   // hi*lo
                mma16bf(acc[j][0], acc[j][1], acc[j][2], acc[j][3],
                        A0.z, A1.z, A0.w, A1.w, Bv.x, Bv.y);   // lo*hi
            }
        }

        // ---- write partial gates to this k-quarter's exchange plane
        float* gxp = gx + kq * (64 * GXS);
#pragma unroll
        for (int j = 0; j < 4; j++) {
            float2 lo2; lo2.x = acc[j][0]; lo2.y = acc[j][1];
            float2 hi2; hi2.x = acc[j][2]; hi2.y = acc[j][3];
            *(float2*)&gxp[(g * 16 + fg) * GXS + 8 * j + 2 * tq] = lo2;
            *(float2*)&gxp[(g * 16 + fg + 8) * GXS + 8 * j + 2 * tq] = hi2;
        }
        __syncthreads();

        // ---- activations: sum 4 k-quarter partials, update state, write h
        float gate[4];
#pragma unroll
        for (int gg = 0; gg < 4; gg++) {
            const int row = (gg * 16 + ml) * GXS + bh;
            gate[gg] = (gx[row] + gx[64 * GXS + row])
                     + (gx[2 * 64 * GXS + row] + gx[3 * 64 * GXS + row]);
        }

        const float gi = gate[0] + pg[0];
        const float gf = gate[1] + pg[1];
        const float gg = gate[2] + pg[2];
        const float go = gate[3] + pg[3];
        const float i_ = __fdividef(1.f, 1.f + __expf(-gi));
        const float f_ = __fdividef(1.f, 1.f + __expf(-gf));
        const float g_ = tanhf(gg);
        const float o_ = __fdividef(1.f, 1.f + __expf(-go));
        const float c = f_ * creg + i_ * g_;
        creg = c;
        const float h = o_ * tanhf(c);
        hpack[(long)b * HID + m] = hpk(h);
        seq[(long)t * STATE + (long)b * HID + m] = h;

        if (t == T_DIM - 1) {
            hT[(long)b * HID + m] = h;
            cT[(long)b * HID + m] = c;
            break;               // no later reader inside this launch
        }

        group_barrier(bb);   // only the 32 blocks sharing this batch range
    }
}

// ============================================================================
// LayerNorm + (t,b)->(b,t) transpose (unchanged).
// ============================================================================
__global__ __launch_bounds__(256) void ln_out_kernel(
    const float* __restrict__ X, const float* __restrict__ gamma,
    const float* __restrict__ beta, float* __restrict__ out)
{
    const int row = blockIdx.x;
    const float* x = X + (long)row * OUT_DIM;
    const int tid = threadIdx.x;

    const float v0 = x[tid];
    const float v1 = x[tid + 256];
    const float v2 = x[tid + 512];

    __shared__ float red[8];
    __shared__ float s_mu, s_rs;

    float s = v0 + v1 + v2;
#pragma unroll
    for (int o = 16; o > 0; o >>= 1) s += __shfl_down_sync(0xffffffffu, s, o);
    if ((tid & 31) == 0) red[tid >> 5] = s;
    __syncthreads();
    if (tid == 0) {
        float tot = 0.f;
#pragma unroll
        for (int i = 0; i < 8; i++) tot += red[i];
        s_mu = tot * (1.f / OUT_DIM);
    }
    __syncthreads();
    const float mu = s_mu;
    const float d0 = v0 - mu, d1 = v1 - mu, d2 = v2 - mu;

    float q = d0 * d0 + d1 * d1 + d2 * d2;
#pragma unroll
    for (int o = 16; o > 0; o >>= 1) q += __shfl_down_sync(0xffffffffu, q, o);
    if ((tid & 31) == 0) red[tid >> 5] = q;
    __syncthreads();
    if (tid == 0) {
        float tot = 0.f;
#pragma unroll
        for (int i = 0; i < 8; i++) tot += red[i];
        s_rs = rsqrtf(tot * (1.f / OUT_DIM) + 1e-5f);
    }
    __syncthreads();
    const float rs = s_rs;

    const int b = row & (B_DIM - 1);
    const int t = row >> 7;
    float* o = out + (long)(b * T_DIM + t) * OUT_DIM;
    o[tid]       = d0 * rs * gamma[tid]       + beta[tid];
    o[tid + 256] = d1 * rs * gamma[tid + 256] + beta[tid + 256];
    o[tid + 512] = d2 * rs * gamma[tid + 512] + beta[tid + 512];
}

// ============================================================================
extern "C" void kernel_launch(void* const* d_in, const int* in_sizes, int n_in,
                              void* d_out, int out_size)
{
    const float* x     = (const float*)d_in[0];
    const float* h0    = (const float*)d_in[1];
    const float* c0    = (const float*)d_in[2];
    const float* W_in  = (const float*)d_in[3];
    const float* b_in  = (const float*)d_in[4];
    const float* W_ih  = (const float*)d_in[5];
    const float* W_hh  = (const float*)d_in[6];
    const float* b_ih  = (const float*)d_in[7];
    const float* b_hh  = (const float*)d_in[8];
    const float* W_out = (const float*)d_in[9];
    const float* b_out = (const float*)d_in[10];
    const float* ln_g  = (const float*)d_in[11];
    const float* ln_b  = (const float*)d_in[12];
    float* out = (float*)d_out;

    float *seqA, *seqB, *gates, *outp;
    uint32_t* hpack;
    cudaGetSymbolAddress((void**)&seqA, g_seqA);
    cudaGetSymbolAddress((void**)&seqB, g_seqB);
    cudaGetSymbolAddress((void**)&gates, g_gates);
    cudaGetSymbolAddress((void**)&outp, g_outp);
    cudaGetSymbolAddress((void**)&hpack, g_hpack);

    const int ws_bytes = 64 * RSTR * 4;                           // 135168
    const int ph2_bytes = 32 * RSTR * 4 + 4 * 64 * GXS * 4;       // 104448
    const int lstm_smem = ws_bytes > ph2_bytes ? ws_bytes : ph2_bytes;
    cudaFuncSetAttribute(lstm_layer_kernel,
                         cudaFuncAttributeMaxDynamicSharedMemorySize, lstm_smem);

    const long OUT_ELEMS = (long)B_DIM * T_DIM * OUT_DIM;

    // 1) input projection with (b,t)->(t,b) transpose (tf32 TC)
    gemm_tf32<<<dim3(ROWS / 128, HID / 128), 256>>>(x, W_in, b_in, nullptr, seqA,
                                                    INP_DIM, HID, 1);

    for (int l = 0; l < NL; l++) {
        const float* in = (l & 1) ? seqB : seqA;
        float* outSeq   = (l & 1) ? seqA : seqB;

        // 2a) parallel: gates = in @ W_ih[l]^T + b_ih[l] + b_hh[l] (tf32 TC)
        gemm_tf32<<<dim3(ROWS / 128, G4 / 128), 256>>>(
            in, W_ih + (long)l * G4 * HID, b_ih + l * G4, b_hh + l * G4,
            gates, HID, G4, 0);

        // 2b) serial recurrence: persistent, bf16-split TC, 16 warps
        lstm_layer_kernel<<<NBLK, 512, lstm_smem>>>(
            h0 + (long)l * STATE, c0 + (long)l * STATE,
            W_hh + (long)l * G4 * HID, gates, outSeq, hpack,
            out + OUT_ELEMS + (long)l * STATE,
            out + OUT_ELEMS + (long)NL * STATE + (long)l * STATE);
    }

    // 3) output projection (tf32 TC)
    gemm_tf32<<<dim3(ROWS / 128, OUT_DIM / 128), 256>>>(seqA, W_out, b_out, nullptr,
                                                        outp, HID, OUT_DIM, 0);

    // 4) layernorm + transpose into d_out
    ln_out_kernel<<<ROWS, 256>>>(outp, ln_g, ln_b, out);
}

// round 15
// speedup vs baseline: 1.1129x; 1.0166x over previous
#include <cuda_runtime.h>
#include <cuda_bf16.h>
#include <math.h>
#include <stdint.h>

#define T_DIM 256
#define B_DIM 128
#define INP_DIM 768
#define HID 512
#define OUT_DIM 768
#define NL 4
#define G4 (4 * HID)            // 2048
#define ROWS (T_DIM * B_DIM)    // 32768
#define STATE (B_DIM * HID)     // 65536

#define NBLK 128                // persistent recurrence grid (<= SM count)
#define NGRP 4                  // independent barrier groups (one per bb)
#define GRP_BLKS 32             // blocks per group
#define GS 24                   // ff-gemm SMEM row stride (floats)

// recurrence chunked SMEM row stride (u32). 528*4 = 2112 B, 2112 mod 128 = 64
// -> every LDS.128 phase (8 lanes) conflict-free.
#define RSTR 528
#define GXS 36                  // gate-exchange stride (floats)

// ---------------- scratch (static device globals: no allocation) ----------------
__device__ float g_seqA[ROWS * HID];
__device__ float g_seqB[ROWS * HID];
__device__ float g_gates[ROWS * G4];
__device__ float g_outp[ROWS * OUT_DIM];
__device__ uint32_t g_hpack[STATE];      // h packed as (bf16 hi | bf16 lo << 16)
__device__ float g_wih4[NL * G4 * HID];  // tf32-pre-rounded W_ih (16 MB)
__device__ float g_wout4[OUT_DIM * HID]; // tf32-pre-rounded W_out

// per-group barrier state, 128B apart (32 u32 stride)
__device__ unsigned int g_bar_cnt4[NGRP * 32];
__device__ unsigned int g_bar_gen4[NGRP * 32];

// ---------------- tf32 helpers (FF GEMM) ----------------
__device__ __forceinline__ uint32_t f2tf(float f) {
    uint32_t u;
    asm("cvt.rna.tf32.f32 %0, %1;" : "=r"(u) : "f"(f));
    return u;
}
__device__ __forceinline__ float f2tff(float f) {
    return __uint_as_float(f2tf(f));
}
// stage one 8-k group WITH tf32 rounding + k-interleave (raw inputs)
__device__ __forceinline__ void st8tf_ilv(float* p, float4 v0, float4 v1) {
    float4 t0, t1;
    t0.x = f2tff(v0.x); t0.y = f2tff(v1.x);
    t0.z = f2tff(v0.y); t0.w = f2tff(v1.y);
    t1.x = f2tff(v0.z); t1.y = f2tff(v1.z);
    t1.z = f2tff(v0.w); t1.w = f2tff(v1.w);
    *(float4*)p = t0;
    *(float4*)(p + 4) = t1;
}
// stage one 8-k group, interleave only (inputs already tf32-rounded)
__device__ __forceinline__ void st8_ilv(float* p, float4 v0, float4 v1) {
    float4 t0, t1;
    t0.x = v0.x; t0.y = v1.x; t0.z = v0.y; t0.w = v1.y;
    t1.x = v0.z; t1.y = v1.z; t1.z = v0.w; t1.w = v1.w;
    *(float4*)p = t0;
    *(float4*)(p + 4) = t1;
}
__device__ __forceinline__ void mma8(float& c0, float& c1, float& c2, float& c3,
                                     uint32_t a0, uint32_t a1, uint32_t a2, uint32_t a3,
                                     uint32_t b0, uint32_t b1) {
    asm volatile("mma.sync.aligned.m16n8k8.row.col.f32.tf32.tf32.f32 "
                 "{%0,%1,%2,%3}, {%4,%5,%6,%7}, {%8,%9}, {%0,%1,%2,%3};"
                 : "+f"(c0), "+f"(c1), "+f"(c2), "+f"(c3)
                 : "r"(a0), "r"(a1), "r"(a2), "r"(a3), "r"(b0), "r"(b1));
}

// ---------------- bf16 helpers (recurrence) ----------------
__device__ __forceinline__ void mma16bf(float& c0, float& c1, float& c2, float& c3,
                                        uint32_t a0, uint32_t a1, uint32_t a2, uint32_t a3,
                                        uint32_t b0, uint32_t b1) {
    asm volatile("mma.sync.aligned.m16n8k16.row.col.f32.bf16.bf16.f32 "
                 "{%0,%1,%2,%3}, {%4,%5,%6,%7}, {%8,%9}, {%0,%1,%2,%3};"
                 : "+f"(c0), "+f"(c1), "+f"(c2), "+f"(c3)
                 : "r"(a0), "r"(a1), "r"(a2), "r"(a3), "r"(b0), "r"(b1));
}
__device__ __forceinline__ uint32_t split_pair(float a, float b, uint32_t& lo) {
    __nv_bfloat16 ah = __float2bfloat16_rn(a);
    __nv_bfloat16 bh = __float2bfloat16_rn(b);
    __nv_bfloat16 al = __float2bfloat16_rn(a - __bfloat162float(ah));
    __nv_bfloat16 bl = __float2bfloat16_rn(b - __bfloat162float(bh));
    lo = (uint32_t)__bfloat16_as_ushort(al) | ((uint32_t)__bfloat16_as_ushort(bl) << 16);
    return (uint32_t)__bfloat16_as_ushort(ah) | ((uint32_t)__bfloat16_as_ushort(bh) << 16);
}
__device__ __forceinline__ uint32_t hpk(float h) {
    __nv_bfloat16 hi = __float2bfloat16_rn(h);
    __nv_bfloat16 lo = __float2bfloat16_rn(h - __bfloat162float(hi));
    return (uint32_t)__bfloat16_as_ushort(hi) | ((uint32_t)__bfloat16_as_ushort(lo) << 16);
}
// fast tanh: 2*sigmoid(2x)-1 via __expf (rel err ~1e-7; saturates correctly)
__device__ __forceinline__ float tanh_fast(float x) {
    const float e = __expf(-2.f * x);
    return __fdividef(2.f, 1.f + e) - 1.f;
}

// Build 4 16B chunks {hi(tq),hi(tq+4),lo(tq),lo(tq+4)} from 16 fp32 values.
__device__ __forceinline__ void make_chunks_f32(const float* v, uint4* out) {
    uint32_t hi[8], lo[8];
#pragma unroll
    for (int p = 0; p < 8; p++) hi[p] = split_pair(v[2 * p], v[2 * p + 1], lo[p]);
#pragma unroll
    for (int tq = 0; tq < 4; tq++) {
        out[tq].x = hi[tq];
        out[tq].y = hi[tq + 4];
        out[tq].z = lo[tq];
        out[tq].w = lo[tq + 4];
    }
}
// Same from 16 hpack-packed u32 values (hi|lo<<16).
__device__ __forceinline__ void make_chunks_pk(const uint32_t* w, uint4* out) {
#pragma unroll
    for (int tq = 0; tq < 4; tq++) {
        const uint32_t a = w[2 * tq],     b = w[2 * tq + 1];
        const uint32_t c = w[2 * tq + 8], d = w[2 * tq + 9];
        out[tq].x = __byte_perm(a, b, 0x5410);
        out[tq].y = __byte_perm(c, d, 0x5410);
        out[tq].z = __byte_perm(a, b, 0x7632);
        out[tq].w = __byte_perm(c, d, 0x7632);
    }
}

// ============================================================================
// One-time per launch: round a weight tensor to tf32 representation.
// ============================================================================
__global__ __launch_bounds__(256) void round_tf32_kernel(
    const float* __restrict__ src, float* __restrict__ dst, int n4)
{
    const int i = blockIdx.x * 256 + threadIdx.x;
    if (i < n4) {
        float4 v = *(const float4*)(src + 4 * i);
        v.x = f2tff(v.x); v.y = f2tff(v.y);
        v.z = f2tff(v.z); v.w = f2tff(v.w);
        *(float4*)(dst + 4 * i) = v;
    }
}

// ============================================================================
// tf32 tensor-core GEMM, 128x128 block tile, 2-stage SMEM double buffering.
// docvt (== xremap path) selects rounding at stage time; otherwise inputs are
// pre-rounded (weights scratch / producer-rounded activations) and staging is
// a pure interleave copy (16 fewer CVT per thread per chunk).
// round_out: round C to tf32 at the epilogue (for seq outputs consumed only
// by later tf32 GEMMs — bit-identical downstream math).
// ============================================================================
__global__ __launch_bounds__(256) void gemm_tf32(
    const float* __restrict__ A, const float* __restrict__ W,
    const float* __restrict__ bias1, const float* __restrict__ bias2,
    float* __restrict__ C, int K, int N, int xremap, int round_out)
{
    __shared__ __align__(16) float As[2][128 * GS];
    __shared__ __align__(16) float Bs[2][128 * GS];

    const int m0 = blockIdx.x * 128;
    const int n0 = blockIdx.y * 128;
    const int tid = threadIdx.x;
    const int lane = tid & 31;
    const int warp = tid >> 5;
    const int gid = lane >> 2;
    const int tig = lane & 3;
    const int wm = (warp >> 2) * 64;
    const int wn = (warp & 3) * 32;

    const int srow = tid >> 1;
    const int skoff = (tid & 1) * 8;
    int arow = m0 + srow;
    if (xremap) {
        const int b = arow & (B_DIM - 1);
        const int t = arow >> 7;
        arow = b * T_DIM + t;
    }
    const float* ag = A + (long)arow * K + skoff;
    const float* bg = W + (long)(n0 + srow) * K + skoff;
    const int soff = srow * GS + skoff;
    const bool docvt = (xremap != 0);

    float acc[4][4][4];
#pragma unroll
    for (int i = 0; i < 4; i++)
#pragma unroll
        for (int j = 0; j < 4; j++)
#pragma unroll
            for (int v = 0; v < 4; v++) acc[i][j][v] = 0.f;

    {
        float4 pa0 = *(const float4*)(ag);
        float4 pa1 = *(const float4*)(ag + 4);
        float4 pb0 = *(const float4*)(bg);
        float4 pb1 = *(const float4*)(bg + 4);
        if (docvt) {
            st8tf_ilv(&As[0][soff], pa0, pa1);
            st8tf_ilv(&Bs[0][soff], pb0, pb1);
        } else {
            st8_ilv(&As[0][soff], pa0, pa1);
            st8_ilv(&Bs[0][soff], pb0, pb1);
        }
    }
    __syncthreads();

    const int nch = K >> 4;
    for (int c = 0; c < nch; c++) {
        const int s = c & 1;
        const bool more = (c + 1 < nch);
        float4 na0, na1, nb0, nb1;
        if (more) {
            const int ko = (c + 1) << 4;
            na0 = *(const float4*)(ag + ko);
            na1 = *(const float4*)(ag + ko + 4);
            nb0 = *(const float4*)(bg + ko);
            nb1 = *(const float4*)(bg + ko + 4);
        }
#pragma unroll
        for (int ks = 0; ks < 16; ks += 8) {
            const int kb = ks + 2 * tig;
            float2 alo[4], ahi[4], bf[4];
#pragma unroll
            for (int i = 0; i < 4; i++) {
                const float* ap = &As[s][(wm + i * 16 + gid) * GS + kb];
                alo[i] = *(const float2*)ap;
                ahi[i] = *(const float2*)(ap + 8 * GS);
            }
#pragma unroll
            for (int j = 0; j < 4; j++)
                bf[j] = *(const float2*)&Bs[s][(wn + j * 8 + gid) * GS + kb];
#pragma unroll
            for (int i = 0; i < 4; i++)
#pragma unroll
                for (int j = 0; j < 4; j++)
                    mma8(acc[i][j][0], acc[i][j][1], acc[i][j][2], acc[i][j][3],
                         __float_as_uint(alo[i].x), __float_as_uint(ahi[i].x),
                         __float_as_uint(alo[i].y), __float_as_uint(ahi[i].y),
                         __float_as_uint(bf[j].x), __float_as_uint(bf[j].y));
        }
        if (more) {
            if (docvt) {
                st8tf_ilv(&As[s ^ 1][soff], na0, na1);
                st8tf_ilv(&Bs[s ^ 1][soff], nb0, nb1);
            } else {
                st8_ilv(&As[s ^ 1][soff], na0, na1);
                st8_ilv(&Bs[s ^ 1][soff], nb0, nb1);
            }
        }
        __syncthreads();
    }

#pragma unroll
    for (int j = 0; j < 4; j++) {
        const int n = n0 + wn + j * 8 + 2 * tig;
        float bz0 = bias1[n], bz1 = bias1[n + 1];
        if (bias2) { bz0 += bias2[n]; bz1 += bias2[n + 1]; }
#pragma unroll
        for (int i = 0; i < 4; i++) {
            const int m = m0 + wm + i * 16 + gid;
            float2 o1; o1.x = acc[i][j][0] + bz0; o1.y = acc[i][j][1] + bz1;
            float2 o2; o2.x = acc[i][j][2] + bz0; o2.y = acc[i][j][3] + bz1;
            if (round_out) {
                o1.x = f2tff(o1.x); o1.y = f2tff(o1.y);
                o2.x = f2tff(o2.x); o2.y = f2tff(o2.y);
            }
            *(float2*)(C + (long)m * N + n) = o1;
            *(float2*)(C + (long)(m + 8) * N + n) = o2;
        }
    }
}

// ============================================================================
// Group barrier: 32 co-resident blocks sharing one bb (batch range).
// ============================================================================
__device__ __forceinline__ void group_barrier(int grp)
{
    __threadfence();
    __syncthreads();
    if (threadIdx.x == 0) {
        volatile unsigned int* genp = &g_bar_gen4[grp * 32];
        const unsigned g = *genp;
        const unsigned a = atomicAdd(&g_bar_cnt4[grp * 32], 1u);
        if (a == GRP_BLKS - 1) {
            g_bar_cnt4[grp * 32] = 0;
            __threadfence();
            *genp = g + 1u;
        } else {
            while (*genp == g) { }
        }
    }
    __syncthreads();
}

// ============================================================================
// Persistent LSTM layer (R14 structure; seq store tf32-rounded at producer,
// tanh via 2*sigmoid(2x)-1).
// ============================================================================
__global__ __launch_bounds__(512, 1) void lstm_layer_kernel(
    const float* __restrict__ h0, const float* __restrict__ c0,
    const float* __restrict__ Whh, const float* __restrict__ gates,
    float* __restrict__ seq, uint32_t* __restrict__ hpack,
    float* __restrict__ hT, float* __restrict__ cT)
{
    extern __shared__ uint32_t smem[];
    uint32_t* ws = smem;                       // phase 1: [64][RSTR]
    uint32_t* hs = smem;                       // phase 2: [32][RSTR]
    float*    gx = (float*)(smem + 32 * RSTR); // phase 2: [4][64][GXS]

    const int tid = threadIdx.x;
    const int lane = tid & 31;
    const int warp = tid >> 5;                 // 0..15
    const int g = warp & 3;                    // gate
    const int kq = warp >> 2;                  // k-quarter 0..3
    const int fg = lane >> 2;                  // fragment group 0..7
    const int tq = lane & 3;

    const int mb = blockIdx.x & 31;
    const int bb = blockIdx.x >> 5;            // barrier group
    const int m0 = mb * 16;
    const int b0 = bb * 32;

    // ---- phase 1: stage W slice into SMEM chunk layout (one-time)
#pragma unroll
    for (int i = 0; i < 4; i++) {
        const int cell = tid + 512 * i;
        const int r = cell >> 5;               // local row 0..63
        const int ks = cell & 31;              // k-chunk 0..31
        const int wg = r >> 4, mli = r & 15;
        const float* wrow = Whh + (long)(wg * HID + m0 + mli) * HID + ks * 16;
        float v[16];
#pragma unroll
        for (int q = 0; q < 4; q++) *(float4*)(v + 4 * q) = *(const float4*)(wrow + 4 * q);
        uint4 ck[4];
        make_chunks_f32(v, ck);
        uint32_t* dst = ws + r * RSTR + ks * 16;
#pragma unroll
        for (int q = 0; q < 4; q++) *(uint4*)(dst + 4 * q) = ck[q];
    }
    __syncthreads();

    // ---- preload A fragments into registers (loop-invariant across t)
    const int ks0 = kq * 8;
    uint4 areg[8][2];
    {
        const uint32_t* wbase = ws + (g * 16) * RSTR;
#pragma unroll
        for (int i = 0; i < 8; i++) {
            const int off = (ks0 + i) * 16 + tq * 4;
            areg[i][0] = *(const uint4*)(wbase + fg * RSTR + off);
            areg[i][1] = *(const uint4*)(wbase + (fg + 8) * RSTR + off);
        }
    }
    __syncthreads();   // ws reads done; smem reused as hs/gx

    // activation roles: thread = (ml 0..15, bh 0..31) -> 1 batch
    const int ml = tid & 15;
    const int bh = tid >> 4;
    const int m = m0 + ml;
    const int b = b0 + bh;

    float creg = c0[(long)b * HID + m];
    const float* preb = gates + (long)b * G4 + m;

    for (int t = 0; t < T_DIM; t++) {
        // prefetch this step's precomputed gate contributions
        const float* pre = preb + (long)t * B_DIM * G4;
        float pg[4];
#pragma unroll
        for (int gg = 0; gg < 4; gg++)
            pg[gg] = __ldcg(pre + (gg << 9));

        // ---- stage h(t-1): 1024 cells / 512 threads
        if (t == 0) {
#pragma unroll
            for (int i = 0; i < 2; i++) {
                const int cell = tid + 512 * i;
                const int sb = cell >> 5;
                const int ks = cell & 31;
                const float* hrow = h0 + (long)(b0 + sb) * HID + ks * 16;
                float v[16];
#pragma unroll
                for (int q = 0; q < 4; q++) *(float4*)(v + 4 * q) = __ldcg((const float4*)(hrow + 4 * q));
                uint4 ck[4];
                make_chunks_f32(v, ck);
                uint32_t* dst = hs + sb * RSTR + ks * 16;
#pragma unroll
                for (int q = 0; q < 4; q++) *(uint4*)(dst + 4 * q) = ck[q];
            }
        } else {
#pragma unroll
            for (int i = 0; i < 2; i++) {
                const int cell = tid + 512 * i;
                const int sb = cell >> 5;
                const int ks = cell & 31;
                const uint32_t* hrow = hpack + (long)(b0 + sb) * HID + ks * 16;
                uint32_t u[16];
#pragma unroll
                for (int q = 0; q < 4; q++) *(uint4*)(u + 4 * q) = __ldcg((const uint4*)(hrow + 4 * q));
                uint4 ck[4];
                make_chunks_pk(u, ck);
                uint32_t* dst = hs + sb * RSTR + ks * 16;
#pragma unroll
                for (int q = 0; q < 4; q++) *(uint4*)(dst + 4 * q) = ck[q];
            }
        }
        __syncthreads();   // hs ready

        // ---- mma: warp computes gate g, k-quarter kq, all 32 batches
        float acc[4][4];
#pragma unroll
        for (int j = 0; j < 4; j++)
#pragma unroll
            for (int v = 0; v < 4; v++) acc[j][v] = 0.f;

#pragma unroll
        for (int i = 0; i < 8; i++) {
            const int off = (ks0 + i) * 16 + tq * 4;
            const uint4 A0 = areg[i][0];
            const uint4 A1 = areg[i][1];
#pragma unroll
            for (int j = 0; j < 4; j++) {
                const uint4 Bv = *(const uint4*)(hs + (8 * j + fg) * RSTR + off);
                mma16bf(acc[j][0], acc[j][1], acc[j][2], acc[j][3],
                        A0.x, A1.x, A0.y, A1.y, Bv.x, Bv.y);   // hi*hi
                mma16bf(acc[j][0], acc[j][1], acc[j][2], acc[j][3],
                        A0.x, A1.x, A0.y, A1.y, Bv.z, Bv.w);   // hi*lo
                mma16bf(acc[j][0], acc[j][1], acc[j][2], acc[j][3],
                        A0.z, A1.z, A0.w, A1.w, Bv.x, Bv.y);   // lo*hi
            }
        }

        // ---- write partial gates to this k-quarter's exchange plane
        float* gxp = gx + kq * (64 * GXS);
#pragma unroll
        for (int j = 0; j < 4; j++) {
            float2 lo2; lo2.x = acc[j][0]; lo2.y = acc[j][1];
            float2 hi2; hi2.x = acc[j][2]; hi2.y = acc[j][3];
            *(float2*)&gxp[(g * 16 + fg) * GXS + 8 * j + 2 * tq] = lo2;
            *(float2*)&gxp[(g * 16 + fg + 8) * GXS + 8 * j + 2 * tq] = hi2;
        }
        __syncthreads();

        // ---- activations: sum 4 k-quarter partials, update state, write h
        float gate[4];
#pragma unroll
        for (int gg = 0; gg < 4; gg++) {
            const int row = (gg * 16 + ml) * GXS + bh;
            gate[gg] = (gx[row] + gx[64 * GXS + row])
                     + (gx[2 * 64 * GXS + row] + gx[3 * 64 * GXS + row]);
        }

        const float gi = gate[0] + pg[0];
        const float gf = gate[1] + pg[1];
        const float gg = gate[2] + pg[2];
        const float go = gate[3] + pg[3];
        const float i_ = __fdividef(1.f, 1.f + __expf(-gi));
        const float f_ = __fdividef(1.f, 1.f + __expf(-gf));
        const float g_ = tanh_fast(gg);
        const float o_ = __fdividef(1.f, 1.f + __expf(-go));
        const float c = f_ * creg + i_ * g_;
        creg = c;
        const float h = o_ * tanh_fast(c);
        hpack[(long)b * HID + m] = hpk(h);
        // seq consumed only by later tf32 GEMMs -> pre-round (identical math)
        seq[(long)t * STATE + (long)b * HID + m] = f2tff(h);

        if (t == T_DIM - 1) {
            hT[(long)b * HID + m] = h;   // full precision to d_out
            cT[(long)b * HID + m] = c;
            break;               // no later reader inside this launch
        }

        group_barrier(bb);   // only the 32 blocks sharing this batch range
    }
}

// ============================================================================
// LayerNorm + (t,b)->(b,t) transpose (unchanged).
// ============================================================================
__global__ __launch_bounds__(256) void ln_out_kernel(
    const float* __restrict__ X, const float* __restrict__ gamma,
    const float* __restrict__ beta, float* __restrict__ out)
{
    const int row = blockIdx.x;
    const float* x = X + (long)row * OUT_DIM;
    const int tid = threadIdx.x;

    const float v0 = x[tid];
    const float v1 = x[tid + 256];
    const float v2 = x[tid + 512];

    __shared__ float red[8];
    __shared__ float s_mu, s_rs;

    float s = v0 + v1 + v2;
#pragma unroll
    for (int o = 16; o > 0; o >>= 1) s += __shfl_down_sync(0xffffffffu, s, o);
    if ((tid & 31) == 0) red[tid >> 5] = s;
    __syncthreads();
    if (tid == 0) {
        float tot = 0.f;
#pragma unroll
        for (int i = 0; i < 8; i++) tot += red[i];
        s_mu = tot * (1.f / OUT_DIM);
    }
    __syncthreads();
    const float mu = s_mu;
    const float d0 = v0 - mu, d1 = v1 - mu, d2 = v2 - mu;

    float q = d0 * d0 + d1 * d1 + d2 * d2;
#pragma unroll
    for (int o = 16; o > 0; o >>= 1) q += __shfl_down_sync(0xffffffffu, q, o);
    if ((tid & 31) == 0) red[tid >> 5] = q;
    __syncthreads();
    if (tid == 0) {
        float tot = 0.f;
#pragma unroll
        for (int i = 0; i < 8; i++) tot += red[i];
        s_rs = rsqrtf(tot * (1.f / OUT_DIM) + 1e-5f);
    }
    __syncthreads();
    const float rs = s_rs;

    const int b = row & (B_DIM - 1);
    const int t = row >> 7;
    float* o = out + (long)(b * T_DIM + t) * OUT_DIM;
    o[tid]       = d0 * rs * gamma[tid]       + beta[tid];
    o[tid + 256] = d1 * rs * gamma[tid + 256] + beta[tid + 256];
    o[tid + 512] = d2 * rs * gamma[tid + 512] + beta[tid + 512];
}

// ============================================================================
extern "C" void kernel_launch(void* const* d_in, const int* in_sizes, int n_in,
                              void* d_out, int out_size)
{
    const float* x     = (const float*)d_in[0];
    const float* h0    = (const float*)d_in[1];
    const float* c0    = (const float*)d_in[2];
    const float* W_in  = (const float*)d_in[3];
    const float* b_in  = (const float*)d_in[4];
    const float* W_ih  = (const float*)d_in[5];
    const float* W_hh  = (const float*)d_in[6];
    const float* b_ih  = (const float*)d_in[7];
    const float* b_hh  = (const float*)d_in[8];
    const float* W_out = (const float*)d_in[9];
    const float* b_out = (const float*)d_in[10];
    const float* ln_g  = (const float*)d_in[11];
    const float* ln_b  = (const float*)d_in[12];
    float* out = (float*)d_out;

    float *seqA, *seqB, *gates, *outp, *wih4, *wout4;
    uint32_t* hpack;
    cudaGetSymbolAddress((void**)&seqA, g_seqA);
    cudaGetSymbolAddress((void**)&seqB, g_seqB);
    cudaGetSymbolAddress((void**)&gates, g_gates);
    cudaGetSymbolAddress((void**)&outp, g_outp);
    cudaGetSymbolAddress((void**)&hpack, g_hpack);
    cudaGetSymbolAddress((void**)&wih4, g_wih4);
    cudaGetSymbolAddress((void**)&wout4, g_wout4);

    const int ws_bytes = 64 * RSTR * 4;                           // 135168
    const int ph2_bytes = 32 * RSTR * 4 + 4 * 64 * GXS * 4;       // 104448
    const int lstm_smem = ws_bytes > ph2_bytes ? ws_bytes : ph2_bytes;
    cudaFuncSetAttribute(lstm_layer_kernel,
                         cudaFuncAttributeMaxDynamicSharedMemorySize, lstm_smem);

    const long OUT_ELEMS = (long)B_DIM * T_DIM * OUT_DIM;

    // 0) pre-round weights to tf32 (once per launch, ~10 us)
    {
        const int n4_ih = NL * G4 * HID / 4;
        const int n4_out = OUT_DIM * HID / 4;
        round_tf32_kernel<<<(n4_ih + 255) / 256, 256>>>(W_ih, wih4, n4_ih);
        round_tf32_kernel<<<(n4_out + 255) / 256, 256>>>(W_out, wout4, n4_out);
    }

    // 1) input projection with (b,t)->(t,b) transpose; cvt at stage (raw x),
    //    round output (seqA consumed only by tf32 GEMM)
    gemm_tf32<<<dim3(ROWS / 128, HID / 128), 256>>>(x, W_in, b_in, nullptr, seqA,
                                                    INP_DIM, HID, 1, 1);

    for (int l = 0; l < NL; l++) {
        const float* in = (l & 1) ? seqB : seqA;
        float* outSeq   = (l & 1) ? seqA : seqB;

        // 2a) gates = in @ W_ih[l]^T + biases; inputs pre-rounded, no cvt,
        //     full-precision output (feeds recurrence adds)
        gemm_tf32<<<dim3(ROWS / 128, G4 / 128), 256>>>(
            in, wih4 + (long)l * G4 * HID, b_ih + l * G4, b_hh + l * G4,
            gates, HID, G4, 0, 0);

        // 2b) serial recurrence: persistent, bf16-split TC, 16 warps
        lstm_layer_kernel<<<NBLK, 512, lstm_smem>>>(
            h0 + (long)l * STATE, c0 + (long)l * STATE,
            W_hh + (long)l * G4 * HID, gates, outSeq, hpack,
            out + OUT_ELEMS + (long)l * STATE,
            out + OUT_ELEMS + (long)NL * STATE + (long)l * STATE);
    }

    // 3) output projection: inputs pre-rounded, no cvt, full-precision out (LN)
    gemm_tf32<<<dim3(ROWS / 128, OUT_DIM / 128), 256>>>(
        seqA, wout4, b_out, nullptr, outp, HID, OUT_DIM, 0, 0);

    // 4) layernorm + transpose into d_out
    ln_out_kernel<<<ROWS, 256>>>(outp, ln_g, ln_b, out);
}

// round 16
// speedup vs baseline: 1.1235x; 1.0096x over previous
#include <cuda_runtime.h>
#include <cuda_bf16.h>
#include <math.h>
#include <stdint.h>

#define T_DIM 256
#define B_DIM 128
#define INP_DIM 768
#define HID 512
#define OUT_DIM 768
#define NL 4
#define G4 (4 * HID)            // 2048
#define ROWS (T_DIM * B_DIM)    // 32768
#define STATE (B_DIM * HID)     // 65536

#define NBLK 128
#define NGRP 4
#define GRP_BLKS 32
#define GS 24                   // ff-gemm SMEM row stride (floats)

#define RSTR 528                // recurrence SMEM row stride (u32)
#define GXS 36

// ---------------- scratch (static device globals: no allocation) ----------------
__device__ float g_seqA[ROWS * HID];
__device__ float g_seqB[ROWS * HID];
__device__ float g_gates[ROWS * G4];
__device__ float g_outp[ROWS * OUT_DIM];
__device__ uint32_t g_hpack[STATE];
__device__ float g_wih4[NL * G4 * HID];  // tf32-rounded + k-interleaved W_ih
__device__ float g_wout4[OUT_DIM * HID]; // tf32-rounded + k-interleaved W_out

__device__ unsigned int g_bar_cnt4[NGRP * 32];
__device__ unsigned int g_bar_gen4[NGRP * 32];

// ---------------- tf32 helpers ----------------
__device__ __forceinline__ uint32_t f2tf(float f) {
    uint32_t u;
    asm("cvt.rna.tf32.f32 %0, %1;" : "=r"(u) : "f"(f));
    return u;
}
__device__ __forceinline__ float f2tff(float f) { return __uint_as_float(f2tf(f)); }
// interleave within an 8-k group: phys(0..7) = k0,k4,k1,k5,k2,k6,k3,k7
__device__ __forceinline__ void st8tf_ilv(float* p, float4 v0, float4 v1) {
    float4 t0, t1;
    t0.x = f2tff(v0.x); t0.y = f2tff(v1.x);
    t0.z = f2tff(v0.y); t0.w = f2tff(v1.y);
    t1.x = f2tff(v0.z); t1.y = f2tff(v1.z);
    t1.z = f2tff(v0.w); t1.w = f2tff(v1.w);
    *(float4*)p = t0;
    *(float4*)(p + 4) = t1;
}
__device__ __forceinline__ void mma8(float& c0, float& c1, float& c2, float& c3,
                                     uint32_t a0, uint32_t a1, uint32_t a2, uint32_t a3,
                                     uint32_t b0, uint32_t b1) {
    asm volatile("mma.sync.aligned.m16n8k8.row.col.f32.tf32.tf32.f32 "
                 "{%0,%1,%2,%3}, {%4,%5,%6,%7}, {%8,%9}, {%0,%1,%2,%3};"
                 : "+f"(c0), "+f"(c1), "+f"(c2), "+f"(c3)
                 : "r"(a0), "r"(a1), "r"(a2), "r"(a3), "r"(b0), "r"(b1));
}
// interleave position: r in [0,8) -> (r<4) ? 2r : 2r-7
__device__ __forceinline__ int ilvpos(int r) { return (r < 4) ? 2 * r : 2 * r - 7; }

// ---------------- cp.async helpers ----------------
__device__ __forceinline__ void cp16(uint32_t saddr, const void* g) {
    asm volatile("cp.async.ca.shared.global [%0], [%1], 16;" :: "r"(saddr), "l"(g));
}
#define CP_COMMIT() asm volatile("cp.async.commit_group;" ::: "memory")
#define CP_WAIT1()  asm volatile("cp.async.wait_group 1;" ::: "memory")

// ---------------- bf16 helpers (recurrence) ----------------
__device__ __forceinline__ void mma16bf(float& c0, float& c1, float& c2, float& c3,
                                        uint32_t a0, uint32_t a1, uint32_t a2, uint32_t a3,
                                        uint32_t b0, uint32_t b1) {
    asm volatile("mma.sync.aligned.m16n8k16.row.col.f32.bf16.bf16.f32 "
                 "{%0,%1,%2,%3}, {%4,%5,%6,%7}, {%8,%9}, {%0,%1,%2,%3};"
                 : "+f"(c0), "+f"(c1), "+f"(c2), "+f"(c3)
                 : "r"(a0), "r"(a1), "r"(a2), "r"(a3), "r"(b0), "r"(b1));
}
__device__ __forceinline__ uint32_t split_pair(float a, float b, uint32_t& lo) {
    __nv_bfloat16 ah = __float2bfloat16_rn(a);
    __nv_bfloat16 bh = __float2bfloat16_rn(b);
    __nv_bfloat16 al = __float2bfloat16_rn(a - __bfloat162float(ah));
    __nv_bfloat16 bl = __float2bfloat16_rn(b - __bfloat162float(bh));
    lo = (uint32_t)__bfloat16_as_ushort(al) | ((uint32_t)__bfloat16_as_ushort(bl) << 16);
    return (uint32_t)__bfloat16_as_ushort(ah) | ((uint32_t)__bfloat16_as_ushort(bh) << 16);
}
__device__ __forceinline__ uint32_t hpk(float h) {
    __nv_bfloat16 hi = __float2bfloat16_rn(h);
    __nv_bfloat16 lo = __float2bfloat16_rn(h - __bfloat162float(hi));
    return (uint32_t)__bfloat16_as_ushort(hi) | ((uint32_t)__bfloat16_as_ushort(lo) << 16);
}
__device__ __forceinline__ float tanh_fast(float x) {
    const float e = __expf(-2.f * x);
    return __fdividef(2.f, 1.f + e) - 1.f;
}
__device__ __forceinline__ void make_chunks_f32(const float* v, uint4* out) {
    uint32_t hi[8], lo[8];
#pragma unroll
    for (int p = 0; p < 8; p++) hi[p] = split_pair(v[2 * p], v[2 * p + 1], lo[p]);
#pragma unroll
    for (int tq = 0; tq < 4; tq++) {
        out[tq].x = hi[tq];
        out[tq].y = hi[tq + 4];
        out[tq].z = lo[tq];
        out[tq].w = lo[tq + 4];
    }
}
__device__ __forceinline__ void make_chunks_pk(const uint32_t* w, uint4* out) {
#pragma unroll
    for (int tq = 0; tq < 4; tq++) {
        const uint32_t a = w[2 * tq],     b = w[2 * tq + 1];
        const uint32_t c = w[2 * tq + 8], d = w[2 * tq + 9];
        out[tq].x = __byte_perm(a, b, 0x5410);
        out[tq].y = __byte_perm(c, d, 0x5410);
        out[tq].z = __byte_perm(a, b, 0x7632);
        out[tq].w = __byte_perm(c, d, 0x7632);
    }
}

// ============================================================================
// Prep: round weights to tf32 AND k-interleave (one 8-group per thread).
// out[8g + p] = round(in[8g + L[p]]), L = {0,4,1,5,2,6,3,7} — identical to
// what st8tf_ilv produced at stage time, so GEMM math is bit-identical.
// ============================================================================
__global__ __launch_bounds__(256) void round_ilv_kernel(
    const float* __restrict__ src, float* __restrict__ dst, long ngroups)
{
    const long i = (long)blockIdx.x * 256 + threadIdx.x;
    if (i < ngroups) {
        const float* s = src + i * 8;
        const float4 a = *(const float4*)s;
        const float4 b = *(const float4*)(s + 4);
        st8tf_ilv(dst + i * 8, a, b);
    }
}

// ============================================================================
// cp.async tf32 GEMM (pre-rounded, pre-interleaved operands).
// 128x128 tile, 8 warps (2m x 4n), warp tile 64x32, k16 chunks, 3-stage
// cp.async pipeline (2 chunks of LDG slack, zero staging registers).
// ============================================================================
__global__ __launch_bounds__(256) void gemm_ca(
    const float* __restrict__ A, const float* __restrict__ W,
    const float* __restrict__ bias1, const float* __restrict__ bias2,
    float* __restrict__ C, int K, int N)
{
    extern __shared__ float gsm[];
    float* As = gsm;                    // [3][128*GS]
    float* Bs = gsm + 3 * 128 * GS;     // [3][128*GS]
    const int STG = 128 * GS;           // floats per stage

    const int m0 = blockIdx.x * 128;
    const int n0 = blockIdx.y * 128;
    const int tid = threadIdx.x;
    const int lane = tid & 31;
    const int warp = tid >> 5;
    const int gid = lane >> 2;
    const int tig = lane & 3;
    const int wm = (warp >> 2) * 64;
    const int wn = (warp & 3) * 32;

    const int srow = tid >> 1;
    const int skoff = (tid & 1) * 8;
    const float* ag = A + (long)(m0 + srow) * K + skoff;
    const float* bg = W + (long)(n0 + srow) * K + skoff;
    const uint32_t as0 = (uint32_t)__cvta_generic_to_shared(As) + (srow * GS + skoff) * 4;
    const uint32_t bs0 = (uint32_t)__cvta_generic_to_shared(Bs) + (srow * GS + skoff) * 4;
    const uint32_t stgb = STG * 4;

    float acc[4][4][4];
#pragma unroll
    for (int i = 0; i < 4; i++)
#pragma unroll
        for (int j = 0; j < 4; j++)
#pragma unroll
            for (int v = 0; v < 4; v++) acc[i][j][v] = 0.f;

    // prologue: stages 0,1 <- chunks 0,1
#pragma unroll
    for (int s = 0; s < 2; s++) {
        cp16(as0 + s * stgb, ag + s * 16);
        cp16(as0 + s * stgb + 16, ag + s * 16 + 4);
        cp16(bs0 + s * stgb, bg + s * 16);
        cp16(bs0 + s * stgb + 16, bg + s * 16 + 4);
        CP_COMMIT();
    }

    const int nch = K >> 4;
    int sbuf = 0, snext = 2;
    for (int c = 0; c < nch; c++) {
        CP_WAIT1();
        __syncthreads();
        const float* Asb = As + sbuf * STG;
        const float* Bsb = Bs + sbuf * STG;
#pragma unroll
        for (int ks = 0; ks < 16; ks += 8) {
            const int kb = ks + 2 * tig;
            float2 alo[4], ahi[4], bf[4];
#pragma unroll
            for (int i = 0; i < 4; i++) {
                const float* ap = &Asb[(wm + i * 16 + gid) * GS + kb];
                alo[i] = *(const float2*)ap;
                ahi[i] = *(const float2*)(ap + 8 * GS);
            }
#pragma unroll
            for (int j = 0; j < 4; j++)
                bf[j] = *(const float2*)&Bsb[(wn + j * 8 + gid) * GS + kb];
#pragma unroll
            for (int i = 0; i < 4; i++)
#pragma unroll
                for (int j = 0; j < 4; j++)
                    mma8(acc[i][j][0], acc[i][j][1], acc[i][j][2], acc[i][j][3],
                         __float_as_uint(alo[i].x), __float_as_uint(ahi[i].x),
                         __float_as_uint(alo[i].y), __float_as_uint(ahi[i].y),
                         __float_as_uint(bf[j].x), __float_as_uint(bf[j].y));
        }
        if (c + 2 < nch) {
            const long ko = (long)(c + 2) * 16;
            cp16(as0 + snext * stgb, ag + ko);
            cp16(as0 + snext * stgb + 16, ag + ko + 4);
            cp16(bs0 + snext * stgb, bg + ko);
            cp16(bs0 + snext * stgb + 16, bg + ko + 4);
        }
        CP_COMMIT();
        sbuf = (sbuf == 2) ? 0 : sbuf + 1;
        snext = (snext == 2) ? 0 : snext + 1;
    }

#pragma unroll
    for (int j = 0; j < 4; j++) {
        const int n = n0 + wn + j * 8 + 2 * tig;
        float bz0 = bias1[n], bz1 = bias1[n + 1];
        if (bias2) { bz0 += bias2[n]; bz1 += bias2[n + 1]; }
#pragma unroll
        for (int i = 0; i < 4; i++) {
            const int m = m0 + wm + i * 16 + gid;
            float2 o1; o1.x = acc[i][j][0] + bz0; o1.y = acc[i][j][1] + bz1;
            float2 o2; o2.x = acc[i][j][2] + bz0; o2.y = acc[i][j][3] + bz1;
            *(float2*)(C + (long)m * N + n) = o1;
            *(float2*)(C + (long)(m + 8) * N + n) = o2;
        }
    }
}
#define GEMM_CA_SMEM (6 * 128 * GS * 4)   // 73,728 B

// ============================================================================
// Legacy tf32 GEMM (in-proj only): raw inputs, cvt at stage, x-transpose remap,
// epilogue rounds + k-interleaves output (seqA feeds cp.async GEMMs).
// ============================================================================
__global__ __launch_bounds__(256) void gemm_tf32(
    const float* __restrict__ A, const float* __restrict__ W,
    const float* __restrict__ bias1, float* __restrict__ C, int K, int N)
{
    __shared__ __align__(16) float As[2][128 * GS];
    __shared__ __align__(16) float Bs[2][128 * GS];

    const int m0 = blockIdx.x * 128;
    const int n0 = blockIdx.y * 128;
    const int tid = threadIdx.x;
    const int lane = tid & 31;
    const int warp = tid >> 5;
    const int gid = lane >> 2;
    const int tig = lane & 3;
    const int wm = (warp >> 2) * 64;
    const int wn = (warp & 3) * 32;

    const int srow = tid >> 1;
    const int skoff = (tid & 1) * 8;
    int arow = m0 + srow;
    {   // x transpose remap: output row t*B+b <- source row b*T+t
        const int b = arow & (B_DIM - 1);
        const int t = arow >> 7;
        arow = b * T_DIM + t;
    }
    const float* ag = A + (long)arow * K + skoff;
    const float* bg = W + (long)(n0 + srow) * K + skoff;
    const int soff = srow * GS + skoff;

    float acc[4][4][4];
#pragma unroll
    for (int i = 0; i < 4; i++)
#pragma unroll
        for (int j = 0; j < 4; j++)
#pragma unroll
            for (int v = 0; v < 4; v++) acc[i][j][v] = 0.f;

    {
        float4 pa0 = *(const float4*)(ag);
        float4 pa1 = *(const float4*)(ag + 4);
        float4 pb0 = *(const float4*)(bg);
        float4 pb1 = *(const float4*)(bg + 4);
        st8tf_ilv(&As[0][soff], pa0, pa1);
        st8tf_ilv(&Bs[0][soff], pb0, pb1);
    }
    __syncthreads();

    const int nch = K >> 4;
    for (int c = 0; c < nch; c++) {
        const int s = c & 1;
        const bool more = (c + 1 < nch);
        float4 na0, na1, nb0, nb1;
        if (more) {
            const int ko = (c + 1) << 4;
            na0 = *(const float4*)(ag + ko);
            na1 = *(const float4*)(ag + ko + 4);
            nb0 = *(const float4*)(bg + ko);
            nb1 = *(const float4*)(bg + ko + 4);
        }
#pragma unroll
        for (int ks = 0; ks < 16; ks += 8) {
            const int kb = ks + 2 * tig;
            float2 alo[4], ahi[4], bf[4];
#pragma unroll
            for (int i = 0; i < 4; i++) {
                const float* ap = &As[s][(wm + i * 16 + gid) * GS + kb];
                alo[i] = *(const float2*)ap;
                ahi[i] = *(const float2*)(ap + 8 * GS);
            }
#pragma unroll
            for (int j = 0; j < 4; j++)
                bf[j] = *(const float2*)&Bs[s][(wn + j * 8 + gid) * GS + kb];
#pragma unroll
            for (int i = 0; i < 4; i++)
#pragma unroll
                for (int j = 0; j < 4; j++)
                    mma8(acc[i][j][0], acc[i][j][1], acc[i][j][2], acc[i][j][3],
                         __float_as_uint(alo[i].x), __float_as_uint(ahi[i].x),
                         __float_as_uint(alo[i].y), __float_as_uint(ahi[i].y),
                         __float_as_uint(bf[j].x), __float_as_uint(bf[j].y));
        }
        if (more) {
            st8tf_ilv(&As[s ^ 1][soff], na0, na1);
            st8tf_ilv(&Bs[s ^ 1][soff], nb0, nb1);
        }
        __syncthreads();
    }

    // epilogue: bias + tf32 round + k-interleave columns (consumed as GEMM k)
#pragma unroll
    for (int j = 0; j < 4; j++) {
        const int n = n0 + wn + j * 8 + 2 * tig;
        const float bz0 = bias1[n], bz1 = bias1[n + 1];
        const int base = n & ~7;
        const int r = n & 7;                 // even
        const int p0 = base + ilvpos(r);
        const int p1 = base + ilvpos(r + 1);
#pragma unroll
        for (int i = 0; i < 4; i++) {
            const int m = m0 + wm + i * 16 + gid;
            C[(long)m * N + p0] = f2tff(acc[i][j][0] + bz0);
            C[(long)m * N + p1] = f2tff(acc[i][j][1] + bz1);
            C[(long)(m + 8) * N + p0] = f2tff(acc[i][j][2] + bz0);
            C[(long)(m + 8) * N + p1] = f2tff(acc[i][j][3] + bz1);
        }
    }
}

// ============================================================================
// Group barrier: 32 co-resident blocks sharing one bb.
// ============================================================================
__device__ __forceinline__ void group_barrier(int grp)
{
    __threadfence();
    __syncthreads();
    if (threadIdx.x == 0) {
        volatile unsigned int* genp = &g_bar_gen4[grp * 32];
        const unsigned g = *genp;
        const unsigned a = atomicAdd(&g_bar_cnt4[grp * 32], 1u);
        if (a == GRP_BLKS - 1) {
            g_bar_cnt4[grp * 32] = 0;
            __threadfence();
            *genp = g + 1u;
        } else {
            while (*genp == g) { }
        }
    }
    __syncthreads();
}

// ============================================================================
// Persistent LSTM layer (R15 structure; seq store now k-interleaved since its
// only consumers are the cp.async GEMMs).
// ============================================================================
__global__ __launch_bounds__(512, 1) void lstm_layer_kernel(
    const float* __restrict__ h0, const float* __restrict__ c0,
    const float* __restrict__ Whh, const float* __restrict__ gates,
    float* __restrict__ seq, uint32_t* __restrict__ hpack,
    float* __restrict__ hT, float* __restrict__ cT)
{
    extern __shared__ uint32_t smem[];
    uint32_t* ws = smem;
    uint32_t* hs = smem;
    float*    gx = (float*)(smem + 32 * RSTR);

    const int tid = threadIdx.x;
    const int lane = tid & 31;
    const int warp = tid >> 5;
    const int g = warp & 3;
    const int kq = warp >> 2;
    const int fg = lane >> 2;
    const int tq = lane & 3;

    const int mb = blockIdx.x & 31;
    const int bb = blockIdx.x >> 5;
    const int m0 = mb * 16;
    const int b0 = bb * 32;

#pragma unroll
    for (int i = 0; i < 4; i++) {
        const int cell = tid + 512 * i;
        const int r = cell >> 5;
        const int ks = cell & 31;
        const int wg = r >> 4, mli = r & 15;
        const float* wrow = Whh + (long)(wg * HID + m0 + mli) * HID + ks * 16;
        float v[16];
#pragma unroll
        for (int q = 0; q < 4; q++) *(float4*)(v + 4 * q) = *(const float4*)(wrow + 4 * q);
        uint4 ck[4];
        make_chunks_f32(v, ck);
        uint32_t* dst = ws + r * RSTR + ks * 16;
#pragma unroll
        for (int q = 0; q < 4; q++) *(uint4*)(dst + 4 * q) = ck[q];
    }
    __syncthreads();

    const int ks0 = kq * 8;
    uint4 areg[8][2];
    {
        const uint32_t* wbase = ws + (g * 16) * RSTR;
#pragma unroll
        for (int i = 0; i < 8; i++) {
            const int off = (ks0 + i) * 16 + tq * 4;
            areg[i][0] = *(const uint4*)(wbase + fg * RSTR + off);
            areg[i][1] = *(const uint4*)(wbase + (fg + 8) * RSTR + off);
        }
    }
    __syncthreads();

    const int ml = tid & 15;
    const int bh = tid >> 4;
    const int m = m0 + ml;
    const int b = b0 + bh;
    const int mphys = (m & ~7) | ilvpos(m & 7);   // interleaved seq column

    float creg = c0[(long)b * HID + m];
    const float* preb = gates + (long)b * G4 + m;

    for (int t = 0; t < T_DIM; t++) {
        const float* pre = preb + (long)t * B_DIM * G4;
        float pg[4];
#pragma unroll
        for (int gg = 0; gg < 4; gg++)
            pg[gg] = __ldcg(pre + (gg << 9));

        if (t == 0) {
#pragma unroll
            for (int i = 0; i < 2; i++) {
                const int cell = tid + 512 * i;
                const int sb = cell >> 5;
                const int ks = cell & 31;
                const float* hrow = h0 + (long)(b0 + sb) * HID + ks * 16;
                float v[16];
#pragma unroll
                for (int q = 0; q < 4; q++) *(float4*)(v + 4 * q) = __ldcg((const float4*)(hrow + 4 * q));
                uint4 ck[4];
                make_chunks_f32(v, ck);
                uint32_t* dst = hs + sb * RSTR + ks * 16;
#pragma unroll
                for (int q = 0; q < 4; q++) *(uint4*)(dst + 4 * q) = ck[q];
            }
        } else {
#pragma unroll
            for (int i = 0; i < 2; i++) {
                const int cell = tid + 512 * i;
                const int sb = cell >> 5;
                const int ks = cell & 31;
                const uint32_t* hrow = hpack + (long)(b0 + sb) * HID + ks * 16;
                uint32_t u[16];
#pragma unroll
                for (int q = 0; q < 4; q++) *(uint4*)(u + 4 * q) = __ldcg((const uint4*)(hrow + 4 * q));
                uint4 ck[4];
                make_chunks_pk(u, ck);
                uint32_t* dst = hs + sb * RSTR + ks * 16;
#pragma unroll
                for (int q = 0; q < 4; q++) *(uint4*)(dst + 4 * q) = ck[q];
            }
        }
        __syncthreads();

        float acc[4][4];
#pragma unroll
        for (int j = 0; j < 4; j++)
#pragma unroll
            for (int v = 0; v < 4; v++) acc[j][v] = 0.f;

#pragma unroll
        for (int i = 0; i < 8; i++) {
            const int off = (ks0 + i) * 16 + tq * 4;
            const uint4 A0 = areg[i][0];
            const uint4 A1 = areg[i][1];
#pragma unroll
            for (int j = 0; j < 4; j++) {
                const uint4 Bv = *(const uint4*)(hs + (8 * j + fg) * RSTR + off);
                mma16bf(acc[j][0], acc[j][1], acc[j][2], acc[j][3],
                        A0.x, A1.x, A0.y, A1.y, Bv.x, Bv.y);
                mma16bf(acc[j][0], acc[j][1], acc[j][2], acc[j][3],
                        A0.x, A1.x, A0.y, A1.y, Bv.z, Bv.w);
                mma16bf(acc[j][0], acc[j][1], acc[j][2], acc[j][3],
                        A0.z, A1.z, A0.w, A1.w, Bv.x, Bv.y);
            }
        }

        float* gxp = gx + kq * (64 * GXS);
#pragma unroll
        for (int j = 0; j < 4; j++) {
            float2 lo2; lo2.x = acc[j][0]; lo2.y = acc[j][1];
            float2 hi2; hi2.x = acc[j][2]; hi2.y = acc[j][3];
            *(float2*)&gxp[(g * 16 + fg) * GXS + 8 * j + 2 * tq] = lo2;
            *(float2*)&gxp[(g * 16 + fg + 8) * GXS + 8 * j + 2 * tq] = hi2;
        }
        __syncthreads();

        float gate[4];
#pragma unroll
        for (int gg = 0; gg < 4; gg++) {
            const int row = (gg * 16 + ml) * GXS + bh;
            gate[gg] = (gx[row] + gx[64 * GXS + row])
                     + (gx[2 * 64 * GXS + row] + gx[3 * 64 * GXS + row]);
        }

        const float gi = gate[0] + pg[0];
        const float gf = gate[1] + pg[1];
        const float gg = gate[2] + pg[2];
        const float go = gate[3] + pg[3];
        const float i_ = __fdividef(1.f, 1.f + __expf(-gi));
        const float f_ = __fdividef(1.f, 1.f + __expf(-gf));
        const float g_ = tanh_fast(gg);
        const float o_ = __fdividef(1.f, 1.f + __expf(-go));
        const float c = f_ * creg + i_ * g_;
        creg = c;
        const float h = o_ * tanh_fast(c);
        hpack[(long)b * HID + m] = hpk(h);
        seq[(long)t * STATE + (long)b * HID + mphys] = f2tff(h);

        if (t == T_DIM - 1) {
            hT[(long)b * HID + m] = h;
            cT[(long)b * HID + m] = c;
            break;
        }

        group_barrier(bb);
    }
}

// ============================================================================
// LayerNorm + (t,b)->(b,t) transpose (unchanged).
// ============================================================================
__global__ __launch_bounds__(256) void ln_out_kernel(
    const float* __restrict__ X, const float* __restrict__ gamma,
    const float* __restrict__ beta, float* __restrict__ out)
{
    const int row = blockIdx.x;
    const float* x = X + (long)row * OUT_DIM;
    const int tid = threadIdx.x;

    const float v0 = x[tid];
    const float v1 = x[tid + 256];
    const float v2 = x[tid + 512];

    __shared__ float red[8];
    __shared__ float s_mu, s_rs;

    float s = v0 + v1 + v2;
#pragma unroll
    for (int o = 16; o > 0; o >>= 1) s += __shfl_down_sync(0xffffffffu, s, o);
    if ((tid & 31) == 0) red[tid >> 5] = s;
    __syncthreads();
    if (tid == 0) {
        float tot = 0.f;
#pragma unroll
        for (int i = 0; i < 8; i++) tot += red[i];
        s_mu = tot * (1.f / OUT_DIM);
    }
    __syncthreads();
    const float mu = s_mu;
    const float d0 = v0 - mu, d1 = v1 - mu, d2 = v2 - mu;

    float q = d0 * d0 + d1 * d1 + d2 * d2;
#pragma unroll
    for (int o = 16; o > 0; o >>= 1) q += __shfl_down_sync(0xffffffffu, q, o);
    if ((tid & 31) == 0) red[tid >> 5] = q;
    __syncthreads();
    if (tid == 0) {
        float tot = 0.f;
#pragma unroll
        for (int i = 0; i < 8; i++) tot += red[i];
        s_rs = rsqrtf(tot * (1.f / OUT_DIM) + 1e-5f);
    }
    __syncthreads();
    const float rs = s_rs;

    const int b = row & (B_DIM - 1);
    const int t = row >> 7;
    float* o = out + (long)(b * T_DIM + t) * OUT_DIM;
    o[tid]       = d0 * rs * gamma[tid]       + beta[tid];
    o[tid + 256] = d1 * rs * gamma[tid + 256] + beta[tid + 256];
    o[tid + 512] = d2 * rs * gamma[tid + 512] + beta[tid + 512];
}

// ============================================================================
extern "C" void kernel_launch(void* const* d_in, const int* in_sizes, int n_in,
                              void* d_out, int out_size)
{
    const float* x     = (const float*)d_in[0];
    const float* h0    = (const float*)d_in[1];
    const float* c0    = (const float*)d_in[2];
    const float* W_in  = (const float*)d_in[3];
    const float* b_in  = (const float*)d_in[4];
    const float* W_ih  = (const float*)d_in[5];
    const float* W_hh  = (const float*)d_in[6];
    const float* b_ih  = (const float*)d_in[7];
    const float* b_hh  = (const float*)d_in[8];
    const float* W_out = (const float*)d_in[9];
    const float* b_out = (const float*)d_in[10];
    const float* ln_g  = (const float*)d_in[11];
    const float* ln_b  = (const float*)d_in[12];
    float* out = (float*)d_out;

    float *seqA, *seqB, *gates, *outp, *wih4, *wout4;
    uint32_t* hpack;
    cudaGetSymbolAddress((void**)&seqA, g_seqA);
    cudaGetSymbolAddress((void**)&seqB, g_seqB);
    cudaGetSymbolAddress((void**)&gates, g_gates);
    cudaGetSymbolAddress((void**)&outp, g_outp);
    cudaGetSymbolAddress((void**)&hpack, g_hpack);
    cudaGetSymbolAddress((void**)&wih4, g_wih4);
    cudaGetSymbolAddress((void**)&wout4, g_wout4);

    const int ws_bytes = 64 * RSTR * 4;
    const int ph2_bytes = 32 * RSTR * 4 + 4 * 64 * GXS * 4;
    const int lstm_smem = ws_bytes > ph2_bytes ? ws_bytes : ph2_bytes;
    cudaFuncSetAttribute(lstm_layer_kernel,
                         cudaFuncAttributeMaxDynamicSharedMemorySize, lstm_smem);
    cudaFuncSetAttribute(gemm_ca,
                         cudaFuncAttributeMaxDynamicSharedMemorySize, GEMM_CA_SMEM);

    const long OUT_ELEMS = (long)B_DIM * T_DIM * OUT_DIM;

    // 0) prep: round + k-interleave weights (once per launch)
    {
        const long ng_ih = (long)NL * G4 * HID / 8;
        const long ng_out = (long)OUT_DIM * HID / 8;
        round_ilv_kernel<<<(int)((ng_ih + 255) / 256), 256>>>(W_ih, wih4, ng_ih);
        round_ilv_kernel<<<(int)((ng_out + 255) / 256), 256>>>(W_out, wout4, ng_out);
    }

    // 1) input projection (legacy path: raw x, transpose remap, ilv output)
    gemm_tf32<<<dim3(ROWS / 128, HID / 128), 256>>>(x, W_in, b_in, seqA,
                                                    INP_DIM, HID);

    for (int l = 0; l < NL; l++) {
        const float* in = (l & 1) ? seqB : seqA;
        float* outSeq   = (l & 1) ? seqA : seqB;

        // 2a) gates GEMM: cp.async pipeline, pre-interleaved operands
        gemm_ca<<<dim3(ROWS / 128, G4 / 128), 256, GEMM_CA_SMEM>>>(
            in, wih4 + (long)l * G4 * HID, b_ih + l * G4, b_hh + l * G4,
            gates, HID, G4);

        // 2b) serial recurrence
        lstm_layer_kernel<<<NBLK, 512, lstm_smem>>>(
            h0 + (long)l * STATE, c0 + (long)l * STATE,
            W_hh + (long)l * G4 * HID, gates, outSeq, hpack,
            out + OUT_ELEMS + (long)l * STATE,
            out + OUT_ELEMS + (long)NL * STATE + (long)l * STATE);
    }

    // 3) output projection: cp.async pipeline
    gemm_ca<<<dim3(ROWS / 128, OUT_DIM / 128), 256, GEMM_CA_SMEM>>>(
        seqA, wout4, b_out, nullptr, outp, HID, OUT_DIM);

    // 4) layernorm + transpose into d_out
    ln_out_kernel<<<ROWS, 256>>>(outp, ln_g, ln_b, out);
}

// round 17
// speedup vs baseline: 1.1496x; 1.0232x over previous
#include <cuda_runtime.h>
#include <cuda_bf16.h>
#include <math.h>
#include <stdint.h>

#define T_DIM 256
#define B_DIM 128
#define INP_DIM 768
#define HID 512
#define OUT_DIM 768
#define NL 4
#define G4 (4 * HID)            // 2048
#define ROWS (T_DIM * B_DIM)    // 32768
#define STATE (B_DIM * HID)     // 65536

#define NBLK 128
#define NGRP 4
#define GRP_BLKS 32
#define GS 24                   // ff-gemm SMEM row stride (floats)

#define RSTR 528                // recurrence SMEM row stride (u32)
#define GXS 36

// ---------------- scratch (static device globals: no allocation) ----------------
__device__ float g_seqA[ROWS * HID];
__device__ float g_seqB[ROWS * HID];
__device__ float g_gates[ROWS * G4];
__device__ float g_outp[ROWS * OUT_DIM];
__device__ uint32_t g_hpack[STATE];
__device__ float g_wih4[NL * G4 * HID];  // tf32-rounded + k-interleaved W_ih
__device__ float g_wout4[OUT_DIM * HID]; // tf32-rounded + k-interleaved W_out

__device__ unsigned int g_bar_cnt4[NGRP * 32];
__device__ unsigned int g_bar_gen4[NGRP * 32];

// ---------------- tf32 helpers ----------------
__device__ __forceinline__ uint32_t f2tf(float f) {
    uint32_t u;
    asm("cvt.rna.tf32.f32 %0, %1;" : "=r"(u) : "f"(f));
    return u;
}
__device__ __forceinline__ float f2tff(float f) { return __uint_as_float(f2tf(f)); }
// interleave within an 8-k group: phys(0..7) = k0,k4,k1,k5,k2,k6,k3,k7
__device__ __forceinline__ void st8tf_ilv(float* p, float4 v0, float4 v1) {
    float4 t0, t1;
    t0.x = f2tff(v0.x); t0.y = f2tff(v1.x);
    t0.z = f2tff(v0.y); t0.w = f2tff(v1.y);
    t1.x = f2tff(v0.z); t1.y = f2tff(v1.z);
    t1.z = f2tff(v0.w); t1.w = f2tff(v1.w);
    *(float4*)p = t0;
    *(float4*)(p + 4) = t1;
}
__device__ __forceinline__ void mma8(float& c0, float& c1, float& c2, float& c3,
                                     uint32_t a0, uint32_t a1, uint32_t a2, uint32_t a3,
                                     uint32_t b0, uint32_t b1) {
    asm volatile("mma.sync.aligned.m16n8k8.row.col.f32.tf32.tf32.f32 "
                 "{%0,%1,%2,%3}, {%4,%5,%6,%7}, {%8,%9}, {%0,%1,%2,%3};"
                 : "+f"(c0), "+f"(c1), "+f"(c2), "+f"(c3)
                 : "r"(a0), "r"(a1), "r"(a2), "r"(a3), "r"(b0), "r"(b1));
}
__device__ __forceinline__ int ilvpos(int r) { return (r < 4) ? 2 * r : 2 * r - 7; }

// ---------------- cp.async helpers ----------------
__device__ __forceinline__ void cp16(uint32_t saddr, const void* g) {
    asm volatile("cp.async.ca.shared.global [%0], [%1], 16;" :: "r"(saddr), "l"(g));
}
#define CP_COMMIT() asm volatile("cp.async.commit_group;" ::: "memory")
#define CP_WAIT2()  asm volatile("cp.async.wait_group 2;" ::: "memory")

// ---------------- bf16 helpers (recurrence) ----------------
__device__ __forceinline__ void mma16bf(float& c0, float& c1, float& c2, float& c3,
                                        uint32_t a0, uint32_t a1, uint32_t a2, uint32_t a3,
                                        uint32_t b0, uint32_t b1) {
    asm volatile("mma.sync.aligned.m16n8k16.row.col.f32.bf16.bf16.f32 "
                 "{%0,%1,%2,%3}, {%4,%5,%6,%7}, {%8,%9}, {%0,%1,%2,%3};"
                 : "+f"(c0), "+f"(c1), "+f"(c2), "+f"(c3)
                 : "r"(a0), "r"(a1), "r"(a2), "r"(a3), "r"(b0), "r"(b1));
}
__device__ __forceinline__ uint32_t split_pair(float a, float b, uint32_t& lo) {
    __nv_bfloat16 ah = __float2bfloat16_rn(a);
    __nv_bfloat16 bh = __float2bfloat16_rn(b);
    __nv_bfloat16 al = __float2bfloat16_rn(a - __bfloat162float(ah));
    __nv_bfloat16 bl = __float2bfloat16_rn(b - __bfloat162float(bh));
    lo = (uint32_t)__bfloat16_as_ushort(al) | ((uint32_t)__bfloat16_as_ushort(bl) << 16);
    return (uint32_t)__bfloat16_as_ushort(ah) | ((uint32_t)__bfloat16_as_ushort(bh) << 16);
}
__device__ __forceinline__ uint32_t hpk(float h) {
    __nv_bfloat16 hi = __float2bfloat16_rn(h);
    __nv_bfloat16 lo = __float2bfloat16_rn(h - __bfloat162float(hi));
    return (uint32_t)__bfloat16_as_ushort(hi) | ((uint32_t)__bfloat16_as_ushort(lo) << 16);
}
__device__ __forceinline__ float tanh_fast(float x) {
    const float e = __expf(-2.f * x);
    return __fdividef(2.f, 1.f + e) - 1.f;
}
__device__ __forceinline__ void make_chunks_f32(const float* v, uint4* out) {
    uint32_t hi[8], lo[8];
#pragma unroll
    for (int p = 0; p < 8; p++) hi[p] = split_pair(v[2 * p], v[2 * p + 1], lo[p]);
#pragma unroll
    for (int tq = 0; tq < 4; tq++) {
        out[tq].x = hi[tq];
        out[tq].y = hi[tq + 4];
        out[tq].z = lo[tq];
        out[tq].w = lo[tq + 4];
    }
}
__device__ __forceinline__ void make_chunks_pk(const uint32_t* w, uint4* out) {
#pragma unroll
    for (int tq = 0; tq < 4; tq++) {
        const uint32_t a = w[2 * tq],     b = w[2 * tq + 1];
        const uint32_t c = w[2 * tq + 8], d = w[2 * tq + 9];
        out[tq].x = __byte_perm(a, b, 0x5410);
        out[tq].y = __byte_perm(c, d, 0x5410);
        out[tq].z = __byte_perm(a, b, 0x7632);
        out[tq].w = __byte_perm(c, d, 0x7632);
    }
}

// ============================================================================
// Prep: round weights to tf32 AND k-interleave (bit-identical to stage-time).
// ============================================================================
__global__ __launch_bounds__(256) void round_ilv_kernel(
    const float* __restrict__ src, float* __restrict__ dst, long ngroups)
{
    const long i = (long)blockIdx.x * 256 + threadIdx.x;
    if (i < ngroups) {
        const float* s = src + i * 8;
        const float4 a = *(const float4*)s;
        const float4 b = *(const float4*)(s + 4);
        st8tf_ilv(dst + i * 8, a, b);
    }
}

// ============================================================================
// cp.async tf32 GEMM, 4-stage pipeline (2 chunks of prefetch slack).
// 128x128 tile, 8 warps (2m x 4n), warp tile 64x32, k16 chunks.
// ============================================================================
__global__ __launch_bounds__(256) void gemm_ca(
    const float* __restrict__ A, const float* __restrict__ W,
    const float* __restrict__ bias1, const float* __restrict__ bias2,
    float* __restrict__ C, int K, int N)
{
    extern __shared__ float gsm[];
    float* As = gsm;                    // [4][128*GS]
    float* Bs = gsm + 4 * 128 * GS;     // [4][128*GS]
    const int STG = 128 * GS;

    const int m0 = blockIdx.x * 128;
    const int n0 = blockIdx.y * 128;
    const int tid = threadIdx.x;
    const int lane = tid & 31;
    const int warp = tid >> 5;
    const int gid = lane >> 2;
    const int tig = lane & 3;
    const int wm = (warp >> 2) * 64;
    const int wn = (warp & 3) * 32;

    const int srow = tid >> 1;
    const int skoff = (tid & 1) * 8;
    const float* ag = A + (long)(m0 + srow) * K + skoff;
    const float* bg = W + (long)(n0 + srow) * K + skoff;
    const uint32_t as0 = (uint32_t)__cvta_generic_to_shared(As) + (srow * GS + skoff) * 4;
    const uint32_t bs0 = (uint32_t)__cvta_generic_to_shared(Bs) + (srow * GS + skoff) * 4;
    const uint32_t stgb = STG * 4;

    float acc[4][4][4];
#pragma unroll
    for (int i = 0; i < 4; i++)
#pragma unroll
        for (int j = 0; j < 4; j++)
#pragma unroll
            for (int v = 0; v < 4; v++) acc[i][j][v] = 0.f;

    // prologue: stages 0,1,2 <- chunks 0,1,2
#pragma unroll
    for (int s = 0; s < 3; s++) {
        cp16(as0 + s * stgb, ag + s * 16);
        cp16(as0 + s * stgb + 16, ag + s * 16 + 4);
        cp16(bs0 + s * stgb, bg + s * 16);
        cp16(bs0 + s * stgb + 16, bg + s * 16 + 4);
        CP_COMMIT();
    }

    const int nch = K >> 4;
    int sbuf = 0, snext = 3;
    for (int c = 0; c < nch; c++) {
        CP_WAIT2();
        __syncthreads();
        const float* Asb = As + sbuf * STG;
        const float* Bsb = Bs + sbuf * STG;
#pragma unroll
        for (int ks = 0; ks < 16; ks += 8) {
            const int kb = ks + 2 * tig;
            float2 alo[4], ahi[4], bf[4];
#pragma unroll
            for (int i = 0; i < 4; i++) {
                const float* ap = &Asb[(wm + i * 16 + gid) * GS + kb];
                alo[i] = *(const float2*)ap;
                ahi[i] = *(const float2*)(ap + 8 * GS);
            }
#pragma unroll
            for (int j = 0; j < 4; j++)
                bf[j] = *(const float2*)&Bsb[(wn + j * 8 + gid) * GS + kb];
#pragma unroll
            for (int i = 0; i < 4; i++)
#pragma unroll
                for (int j = 0; j < 4; j++)
                    mma8(acc[i][j][0], acc[i][j][1], acc[i][j][2], acc[i][j][3],
                         __float_as_uint(alo[i].x), __float_as_uint(ahi[i].x),
                         __float_as_uint(alo[i].y), __float_as_uint(ahi[i].y),
                         __float_as_uint(bf[j].x), __float_as_uint(bf[j].y));
        }
        if (c + 3 < nch) {
            const long ko = (long)(c + 3) * 16;
            cp16(as0 + snext * stgb, ag + ko);
            cp16(as0 + snext * stgb + 16, ag + ko + 4);
            cp16(bs0 + snext * stgb, bg + ko);
            cp16(bs0 + snext * stgb + 16, bg + ko + 4);
        }
        CP_COMMIT();
        sbuf = (sbuf + 1) & 3;
        snext = (snext + 1) & 3;
    }

#pragma unroll
    for (int j = 0; j < 4; j++) {
        const int n = n0 + wn + j * 8 + 2 * tig;
        float bz0 = bias1[n], bz1 = bias1[n + 1];
        if (bias2) { bz0 += bias2[n]; bz1 += bias2[n + 1]; }
#pragma unroll
        for (int i = 0; i < 4; i++) {
            const int m = m0 + wm + i * 16 + gid;
            float2 o1; o1.x = acc[i][j][0] + bz0; o1.y = acc[i][j][1] + bz1;
            float2 o2; o2.x = acc[i][j][2] + bz0; o2.y = acc[i][j][3] + bz1;
            *(float2*)(C + (long)m * N + n) = o1;
            *(float2*)(C + (long)(m + 8) * N + n) = o2;
        }
    }
}
#define GEMM_CA_SMEM (8 * 128 * GS * 4)   // 98,304 B (4 stages A + 4 stages B)

// ============================================================================
// Legacy tf32 GEMM (in-proj only): raw x, cvt at stage, transpose remap,
// epilogue rounds + k-interleaves output.
// ============================================================================
__global__ __launch_bounds__(256) void gemm_tf32(
    const float* __restrict__ A, const float* __restrict__ W,
    const float* __restrict__ bias1, float* __restrict__ C, int K, int N)
{
    __shared__ __align__(16) float As[2][128 * GS];
    __shared__ __align__(16) float Bs[2][128 * GS];

    const int m0 = blockIdx.x * 128;
    const int n0 = blockIdx.y * 128;
    const int tid = threadIdx.x;
    const int lane = tid & 31;
    const int warp = tid >> 5;
    const int gid = lane >> 2;
    const int tig = lane & 3;
    const int wm = (warp >> 2) * 64;
    const int wn = (warp & 3) * 32;

    const int srow = tid >> 1;
    const int skoff = (tid & 1) * 8;
    int arow = m0 + srow;
    {
        const int b = arow & (B_DIM - 1);
        const int t = arow >> 7;
        arow = b * T_DIM + t;
    }
    const float* ag = A + (long)arow * K + skoff;
    const float* bg = W + (long)(n0 + srow) * K + skoff;
    const int soff = srow * GS + skoff;

    float acc[4][4][4];
#pragma unroll
    for (int i = 0; i < 4; i++)
#pragma unroll
        for (int j = 0; j < 4; j++)
#pragma unroll
            for (int v = 0; v < 4; v++) acc[i][j][v] = 0.f;

    {
        float4 pa0 = *(const float4*)(ag);
        float4 pa1 = *(const float4*)(ag + 4);
        float4 pb0 = *(const float4*)(bg);
        float4 pb1 = *(const float4*)(bg + 4);
        st8tf_ilv(&As[0][soff], pa0, pa1);
        st8tf_ilv(&Bs[0][soff], pb0, pb1);
    }
    __syncthreads();

    const int nch = K >> 4;
    for (int c = 0; c < nch; c++) {
        const int s = c & 1;
        const bool more = (c + 1 < nch);
        float4 na0, na1, nb0, nb1;
        if (more) {
            const int ko = (c + 1) << 4;
            na0 = *(const float4*)(ag + ko);
            na1 = *(const float4*)(ag + ko + 4);
            nb0 = *(const float4*)(bg + ko);
            nb1 = *(const float4*)(bg + ko + 4);
        }
#pragma unroll
        for (int ks = 0; ks < 16; ks += 8) {
            const int kb = ks + 2 * tig;
            float2 alo[4], ahi[4], bf[4];
#pragma unroll
            for (int i = 0; i < 4; i++) {
                const float* ap = &As[s][(wm + i * 16 + gid) * GS + kb];
                alo[i] = *(const float2*)ap;
                ahi[i] = *(const float2*)(ap + 8 * GS);
            }
#pragma unroll
            for (int j = 0; j < 4; j++)
                bf[j] = *(const float2*)&Bs[s][(wn + j * 8 + gid) * GS + kb];
#pragma unroll
            for (int i = 0; i < 4; i++)
#pragma unroll
                for (int j = 0; j < 4; j++)
                    mma8(acc[i][j][0], acc[i][j][1], acc[i][j][2], acc[i][j][3],
                         __float_as_uint(alo[i].x), __float_as_uint(ahi[i].x),
                         __float_as_uint(alo[i].y), __float_as_uint(ahi[i].y),
                         __float_as_uint(bf[j].x), __float_as_uint(bf[j].y));
        }
        if (more) {
            st8tf_ilv(&As[s ^ 1][soff], na0, na1);
            st8tf_ilv(&Bs[s ^ 1][soff], nb0, nb1);
        }
        __syncthreads();
    }

#pragma unroll
    for (int j = 0; j < 4; j++) {
        const int n = n0 + wn + j * 8 + 2 * tig;
        const float bz0 = bias1[n], bz1 = bias1[n + 1];
        const int base = n & ~7;
        const int r = n & 7;
        const int p0 = base + ilvpos(r);
        const int p1 = base + ilvpos(r + 1);
#pragma unroll
        for (int i = 0; i < 4; i++) {
            const int m = m0 + wm + i * 16 + gid;
            C[(long)m * N + p0] = f2tff(acc[i][j][0] + bz0);
            C[(long)m * N + p1] = f2tff(acc[i][j][1] + bz1);
            C[(long)(m + 8) * N + p0] = f2tff(acc[i][j][2] + bz0);
            C[(long)(m + 8) * N + p1] = f2tff(acc[i][j][3] + bz1);
        }
    }
}

// ============================================================================
// Split group barrier (32 co-resident blocks per bb group).
// arrive: at end of step, after hpack stores. Leader reads gen BEFORE its own
// arrive (stable: gen bumps only after all 32 arrive), returns it.
// wait: top of next step, AFTER the pg LDGs are issued — spin overlaps gmem
// latency. Counter resets inside; gen monotone across graph replays.
// ============================================================================
__device__ __forceinline__ unsigned group_arrive(int grp)
{
    __threadfence();
    __syncthreads();
    unsigned g = 0;
    if (threadIdx.x == 0) {
        volatile unsigned int* genp = &g_bar_gen4[grp * 32];
        g = *genp;
        const unsigned a = atomicAdd(&g_bar_cnt4[grp * 32], 1u);
        if (a == GRP_BLKS - 1) {
            g_bar_cnt4[grp * 32] = 0;
            __threadfence();
            *genp = g + 1u;
        }
    }
    return g;
}
__device__ __forceinline__ void group_wait(unsigned g, int grp)
{
    if (threadIdx.x == 0) {
        volatile unsigned int* genp = &g_bar_gen4[grp * 32];
        while (*genp == g) { }
    }
    __syncthreads();
}

// ============================================================================
// Persistent LSTM layer (R16 structure + split barrier).
// ============================================================================
__global__ __launch_bounds__(512, 1) void lstm_layer_kernel(
    const float* __restrict__ h0, const float* __restrict__ c0,
    const float* __restrict__ Whh, const float* __restrict__ gates,
    float* __restrict__ seq, uint32_t* __restrict__ hpack,
    float* __restrict__ hT, float* __restrict__ cT)
{
    extern __shared__ uint32_t smem[];
    uint32_t* ws = smem;
    uint32_t* hs = smem;
    float*    gx = (float*)(smem + 32 * RSTR);

    const int tid = threadIdx.x;
    const int lane = tid & 31;
    const int warp = tid >> 5;
    const int g = warp & 3;
    const int kq = warp >> 2;
    const int fg = lane >> 2;
    const int tq = lane & 3;

    const int mb = blockIdx.x & 31;
    const int bb = blockIdx.x >> 5;
    const int m0 = mb * 16;
    const int b0 = bb * 32;

#pragma unroll
    for (int i = 0; i < 4; i++) {
        const int cell = tid + 512 * i;
        const int r = cell >> 5;
        const int ks = cell & 31;
        const int wg = r >> 4, mli = r & 15;
        const float* wrow = Whh + (long)(wg * HID + m0 + mli) * HID + ks * 16;
        float v[16];
#pragma unroll
        for (int q = 0; q < 4; q++) *(float4*)(v + 4 * q) = *(const float4*)(wrow + 4 * q);
        uint4 ck[4];
        make_chunks_f32(v, ck);
        uint32_t* dst = ws + r * RSTR + ks * 16;
#pragma unroll
        for (int q = 0; q < 4; q++) *(uint4*)(dst + 4 * q) = ck[q];
    }
    __syncthreads();

    const int ks0 = kq * 8;
    uint4 areg[8][2];
    {
        const uint32_t* wbase = ws + (g * 16) * RSTR;
#pragma unroll
        for (int i = 0; i < 8; i++) {
            const int off = (ks0 + i) * 16 + tq * 4;
            areg[i][0] = *(const uint4*)(wbase + fg * RSTR + off);
            areg[i][1] = *(const uint4*)(wbase + (fg + 8) * RSTR + off);
        }
    }
    __syncthreads();

    const int ml = tid & 15;
    const int bh = tid >> 4;
    const int m = m0 + ml;
    const int b = b0 + bh;
    const int mphys = (m & ~7) | ilvpos(m & 7);

    float creg = c0[(long)b * HID + m];
    const float* preb = gates + (long)b * G4 + m;

    unsigned bgen = 0;
    for (int t = 0; t < T_DIM; t++) {
        // issue this step's gate-prefetch LDGs BEFORE the barrier wait
        const float* pre = preb + (long)t * B_DIM * G4;
        float pg[4];
#pragma unroll
        for (int gg = 0; gg < 4; gg++)
            pg[gg] = __ldcg(pre + (gg << 9));

        if (t > 0) group_wait(bgen, bb);   // spin overlaps pg latency

        if (t == 0) {
#pragma unroll
            for (int i = 0; i < 2; i++) {
                const int cell = tid + 512 * i;
                const int sb = cell >> 5;
                const int ks = cell & 31;
                const float* hrow = h0 + (long)(b0 + sb) * HID + ks * 16;
                float v[16];
#pragma unroll
                for (int q = 0; q < 4; q++) *(float4*)(v + 4 * q) = __ldcg((const float4*)(hrow + 4 * q));
                uint4 ck[4];
                make_chunks_f32(v, ck);
                uint32_t* dst = hs + sb * RSTR + ks * 16;
#pragma unroll
                for (int q = 0; q < 4; q++) *(uint4*)(dst + 4 * q) = ck[q];
            }
        } else {
#pragma unroll
            for (int i = 0; i < 2; i++) {
                const int cell = tid + 512 * i;
                const int sb = cell >> 5;
                const int ks = cell & 31;
                const uint32_t* hrow = hpack + (long)(b0 + sb) * HID + ks * 16;
                uint32_t u[16];
#pragma unroll
                for (int q = 0; q < 4; q++) *(uint4*)(u + 4 * q) = __ldcg((const uint4*)(hrow + 4 * q));
                uint4 ck[4];
                make_chunks_pk(u, ck);
                uint32_t* dst = hs + sb * RSTR + ks * 16;
#pragma unroll
                for (int q = 0; q < 4; q++) *(uint4*)(dst + 4 * q) = ck[q];
            }
        }
        __syncthreads();

        float acc[4][4];
#pragma unroll
        for (int j = 0; j < 4; j++)
#pragma unroll
            for (int v = 0; v < 4; v++) acc[j][v] = 0.f;

#pragma unroll
        for (int i = 0; i < 8; i++) {
            const int off = (ks0 + i) * 16 + tq * 4;
            const uint4 A0 = areg[i][0];
            const uint4 A1 = areg[i][1];
#pragma unroll
            for (int j = 0; j < 4; j++) {
                const uint4 Bv = *(const uint4*)(hs + (8 * j + fg) * RSTR + off);
                mma16bf(acc[j][0], acc[j][1], acc[j][2], acc[j][3],
                        A0.x, A1.x, A0.y, A1.y, Bv.x, Bv.y);
                mma16bf(acc[j][0], acc[j][1], acc[j][2], acc[j][3],
                        A0.x, A1.x, A0.y, A1.y, Bv.z, Bv.w);
                mma16bf(acc[j][0], acc[j][1], acc[j][2], acc[j][3],
                        A0.z, A1.z, A0.w, A1.w, Bv.x, Bv.y);
            }
        }

        float* gxp = gx + kq * (64 * GXS);
#pragma unroll
        for (int j = 0; j < 4; j++) {
            float2 lo2; lo2.x = acc[j][0]; lo2.y = acc[j][1];
            float2 hi2; hi2.x = acc[j][2]; hi2.y = acc[j][3];
            *(float2*)&gxp[(g * 16 + fg) * GXS + 8 * j + 2 * tq] = lo2;
            *(float2*)&gxp[(g * 16 + fg + 8) * GXS + 8 * j + 2 * tq] = hi2;
        }
        __syncthreads();

        float gate[4];
#pragma unroll
        for (int gg = 0; gg < 4; gg++) {
            const int row = (gg * 16 + ml) * GXS + bh;
            gate[gg] = (gx[row] + gx[64 * GXS + row])
                     + (gx[2 * 64 * GXS + row] + gx[3 * 64 * GXS + row]);
        }

        const float gi = gate[0] + pg[0];
        const float gf = gate[1] + pg[1];
        const float gg = gate[2] + pg[2];
        const float go = gate[3] + pg[3];
        const float i_ = __fdividef(1.f, 1.f + __expf(-gi));
        const float f_ = __fdividef(1.f, 1.f + __expf(-gf));
        const float g_ = tanh_fast(gg);
        const float o_ = __fdividef(1.f, 1.f + __expf(-go));
        const float c = f_ * creg + i_ * g_;
        creg = c;
        const float h = o_ * tanh_fast(c);
        hpack[(long)b * HID + m] = hpk(h);
        seq[(long)t * STATE + (long)b * HID + mphys] = f2tff(h);

        if (t == T_DIM - 1) {
            hT[(long)b * HID + m] = h;
            cT[(long)b * HID + m] = c;
            break;
        }

        bgen = group_arrive(bb);   // publish h(t); wait deferred to next top
    }
}

// ============================================================================
// LayerNorm + (t,b)->(b,t) transpose (unchanged).
// ============================================================================
__global__ __launch_bounds__(256) void ln_out_kernel(
    const float* __restrict__ X, const float* __restrict__ gamma,
    const float* __restrict__ beta, float* __restrict__ out)
{
    const int row = blockIdx.x;
    const float* x = X + (long)row * OUT_DIM;
    const int tid = threadIdx.x;

    const float v0 = x[tid];
    const float v1 = x[tid + 256];
    const float v2 = x[tid + 512];

    __shared__ float red[8];
    __shared__ float s_mu, s_rs;

    float s = v0 + v1 + v2;
#pragma unroll
    for (int o = 16; o > 0; o >>= 1) s += __shfl_down_sync(0xffffffffu, s, o);
    if ((tid & 31) == 0) red[tid >> 5] = s;
    __syncthreads();
    if (tid == 0) {
        float tot = 0.f;
#pragma unroll
        for (int i = 0; i < 8; i++) tot += red[i];
        s_mu = tot * (1.f / OUT_DIM);
    }
    __syncthreads();
    const float mu = s_mu;
    const float d0 = v0 - mu, d1 = v1 - mu, d2 = v2 - mu;

    float q = d0 * d0 + d1 * d1 + d2 * d2;
#pragma unroll
    for (int o = 16; o > 0; o >>= 1) q += __shfl_down_sync(0xffffffffu, q, o);
    if ((tid & 31) == 0) red[tid >> 5] = q;
    __syncthreads();
    if (tid == 0) {
        float tot = 0.f;
#pragma unroll
        for (int i = 0; i < 8; i++) tot += red[i];
        s_rs = rsqrtf(tot * (1.f / OUT_DIM) + 1e-5f);
    }
    __syncthreads();
    const float rs = s_rs;

    const int b = row & (B_DIM - 1);
    const int t = row >> 7;
    float* o = out + (long)(b * T_DIM + t) * OUT_DIM;
    o[tid]       = d0 * rs * gamma[tid]       + beta[tid];
    o[tid + 256] = d1 * rs * gamma[tid + 256] + beta[tid + 256];
    o[tid + 512] = d2 * rs * gamma[tid + 512] + beta[tid + 512];
}

// ============================================================================
extern "C" void kernel_launch(void* const* d_in, const int* in_sizes, int n_in,
                              void* d_out, int out_size)
{
    const float* x     = (const float*)d_in[0];
    const float* h0    = (const float*)d_in[1];
    const float* c0    = (const float*)d_in[2];
    const float* W_in  = (const float*)d_in[3];
    const float* b_in  = (const float*)d_in[4];
    const float* W_ih  = (const float*)d_in[5];
    const float* W_hh  = (const float*)d_in[6];
    const float* b_ih  = (const float*)d_in[7];
    const float* b_hh  = (const float*)d_in[8];
    const float* W_out = (const float*)d_in[9];
    const float* b_out = (const float*)d_in[10];
    const float* ln_g  = (const float*)d_in[11];
    const float* ln_b  = (const float*)d_in[12];
    float* out = (float*)d_out;

    float *seqA, *seqB, *gates, *outp, *wih4, *wout4;
    uint32_t* hpack;
    cudaGetSymbolAddress((void**)&seqA, g_seqA);
    cudaGetSymbolAddress((void**)&seqB, g_seqB);
    cudaGetSymbolAddress((void**)&gates, g_gates);
    cudaGetSymbolAddress((void**)&outp, g_outp);
    cudaGetSymbolAddress((void**)&hpack, g_hpack);
    cudaGetSymbolAddress((void**)&wih4, g_wih4);
    cudaGetSymbolAddress((void**)&wout4, g_wout4);

    const int ws_bytes = 64 * RSTR * 4;
    const int ph2_bytes = 32 * RSTR * 4 + 4 * 64 * GXS * 4;
    const int lstm_smem = ws_bytes > ph2_bytes ? ws_bytes : ph2_bytes;
    cudaFuncSetAttribute(lstm_layer_kernel,
                         cudaFuncAttributeMaxDynamicSharedMemorySize, lstm_smem);
    cudaFuncSetAttribute(gemm_ca,
                         cudaFuncAttributeMaxDynamicSharedMemorySize, GEMM_CA_SMEM);

    const long OUT_ELEMS = (long)B_DIM * T_DIM * OUT_DIM;

    // 0) prep: round + k-interleave weights (once per launch)
    {
        const long ng_ih = (long)NL * G4 * HID / 8;
        const long ng_out = (long)OUT_DIM * HID / 8;
        round_ilv_kernel<<<(int)((ng_ih + 255) / 256), 256>>>(W_ih, wih4, ng_ih);
        round_ilv_kernel<<<(int)((ng_out + 255) / 256), 256>>>(W_out, wout4, ng_out);
    }

    // 1) input projection (legacy path: raw x, transpose remap, ilv output)
    gemm_tf32<<<dim3(ROWS / 128, HID / 128), 256>>>(x, W_in, b_in, seqA,
                                                    INP_DIM, HID);

    for (int l = 0; l < NL; l++) {
        const float* in = (l & 1) ? seqB : seqA;
        float* outSeq   = (l & 1) ? seqA : seqB;

        // 2a) gates GEMM: 4-stage cp.async pipeline
        gemm_ca<<<dim3(ROWS / 128, G4 / 128), 256, GEMM_CA_SMEM>>>(
            in, wih4 + (long)l * G4 * HID, b_ih + l * G4, b_hh + l * G4,
            gates, HID, G4);

        // 2b) serial recurrence (split barrier: wait overlapped with pg loads)
        lstm_layer_kernel<<<NBLK, 512, lstm_smem>>>(
            h0 + (long)l * STATE, c0 + (long)l * STATE,
            W_hh + (long)l * G4 * HID, gates, outSeq, hpack,
            out + OUT_ELEMS + (long)l * STATE,
            out + OUT_ELEMS + (long)NL * STATE + (long)l * STATE);
    }

    // 3) output projection: 4-stage cp.async pipeline
    gemm_ca<<<dim3(ROWS / 128, OUT_DIM / 128), 256, GEMM_CA_SMEM>>>(
        seqA, wout4, b_out, nullptr, outp, HID, OUT_DIM);

    // 4) layernorm + transpose into d_out
    ln_out_kernel<<<ROWS, 256>>>(outp, ln_g, ln_b, out);
}